// round 1
// baseline (speedup 1.0000x reference)
#include <cuda_runtime.h>
#include <math.h>

// Problem constants
#define BB   8
#define NN   16384
#define KK   16
#define CC   64
#define MM   32
#define HH   32
#define HID  128
#define NPTS (BB*NN)          // 131072
#define BN_EPS 1e-5f

// Scratch (point-major layouts: [pt][C])
__device__ float g_f1[(size_t)NPTS*CC];
__device__ float g_f2[(size_t)NPTS*CC];
__device__ float g_base[(size_t)NPTS*CC];

struct P1 {
    const float *f, *dp, *dirv;
    const float *de_w1, *de_g1, *de_b1, *de_m1, *de_v1, *de_w2, *de_bias2;
    const float *w1, *b1, *w2, *b2, *w3, *b3;
    const float *agg_g, *agg_b, *agg_m, *agg_v;
};

struct P2 {
    const int*   qidx;
    const float *agg_g, *agg_v;
    const float *mw1, *mg, *mb, *mm, *mv, *mw2;
    float* out;
};

// ---------------------------------------------------------------------------
// Kernel 1: thread-per-point.
//   theta_max -> DE mlp (pe), f1/f2/f3 = W*f+b, write f1,f2 point-major and
//   base = f + pe + scaleA*(f2+f3) + shiftA   (BN folded affine)
// ---------------------------------------------------------------------------
__global__ __launch_bounds__(256) void k1(P1 p) {
    extern __shared__ float sm[];
    float* sw1   = sm;              // 4096
    float* sw2   = sw1  + 4096;     // 4096
    float* sw3   = sw2  + 4096;     // 4096
    float* sdw1  = sw3  + 4096;     // 1024  (H x M)
    float* sdw2  = sdw1 + 1024;     // 2048  (C x H)
    float* sv0   = sdw2 + 2048;     // 32
    float* sv1   = sv0  + 32;
    float* sv2   = sv1  + 32;
    float* sb1   = sv2  + 32;       // 64
    float* sb2   = sb1  + 64;
    float* sb3   = sb2  + 64;
    float* sbias2= sb3  + 64;
    float* ssc1  = sbias2 + 64;     // 32
    float* ssh1  = ssc1 + 32;
    float* sscA  = ssh1 + 32;       // 64
    float* sshA  = sscA + 64;

    const int tid = threadIdx.x;
    for (int i = tid; i < 4096; i += 256) { sw1[i]=p.w1[i]; sw2[i]=p.w2[i]; sw3[i]=p.w3[i]; }
    for (int i = tid; i < 1024; i += 256) sdw1[i] = p.de_w1[i];
    for (int i = tid; i < 2048; i += 256) sdw2[i] = p.de_w2[i];
    if (tid < 64) {
        sb1[tid]=p.b1[tid]; sb2[tid]=p.b2[tid]; sb3[tid]=p.b3[tid];
        sbias2[tid]=p.de_bias2[tid];
        float sc = p.agg_g[tid]*rsqrtf(p.agg_v[tid]+BN_EPS);
        sscA[tid]=sc; sshA[tid]=p.agg_b[tid]-p.agg_m[tid]*sc;
    }
    if (tid < 32) {
        float v0=p.dirv[tid*3+0], v1=p.dirv[tid*3+1], v2=p.dirv[tid*3+2];
        float inv = 1.f/fmaxf(sqrtf(v0*v0+v1*v1+v2*v2), 1e-12f);
        sv0[tid]=v0*inv; sv1[tid]=v1*inv; sv2[tid]=v2*inv;
        float sc = p.de_g1[tid]*rsqrtf(p.de_v1[tid]+BN_EPS);
        ssc1[tid]=sc; ssh1[tid]=p.de_b1[tid]-p.de_m1[tid]*sc;
    }
    __syncthreads();

    const int pt = blockIdx.x*256 + tid;
    const int b  = pt >> 14;            // N = 2^14
    const int n  = pt & (NN-1);

    // ---- theta_max over k ----
    float tm[MM];
#pragma unroll
    for (int m = 0; m < MM; m++) tm[m] = -INFINITY;
    const float* dpb = p.dp + (size_t)b*3*NN*KK + (size_t)n*KK;
#pragma unroll 1
    for (int k = 0; k < KK; k++) {
        float x0 = dpb[k];
        float x1 = dpb[(size_t)NN*KK + k];
        float x2 = dpb[(size_t)2*NN*KK + k];
        float inv = 1.f/fmaxf(sqrtf(x0*x0+x1*x1+x2*x2), 1e-12f);
        x0*=inv; x1*=inv; x2*=inv;
#pragma unroll
        for (int m = 0; m < MM; m++) {
            float val = sv0[m]*x0 + sv1[m]*x1 + sv2[m]*x2;
            tm[m] = fmaxf(tm[m], val);
        }
    }

    // ---- h = gelu(bn1(de_w1 @ tm)) ----
    float h[HH];
    const float4* sdw1_4 = (const float4*)sdw1;
#pragma unroll
    for (int j = 0; j < HH; j++) {
        float acc = 0.f;
#pragma unroll
        for (int m4 = 0; m4 < 8; m4++) {
            float4 w = sdw1_4[j*8 + m4];
            acc += w.x*tm[4*m4] + w.y*tm[4*m4+1] + w.z*tm[4*m4+2] + w.w*tm[4*m4+3];
        }
        float y = acc*ssc1[j] + ssh1[j];
        h[j] = y * normcdff(y);           // exact GELU
    }

    // ---- load f row into registers ----
    float fv[CC];
    const float* fb = p.f + (size_t)b*CC*NN + n;
#pragma unroll
    for (int i = 0; i < CC; i++) fv[i] = fb[(size_t)i*NN];

    const float4* sw1_4 = (const float4*)sw1;
    const float4* sw2_4 = (const float4*)sw2;
    const float4* sw3_4 = (const float4*)sw3;
    const float4* sdw2_4= (const float4*)sdw2;

    float* o1 = g_f1   + (size_t)pt*CC;
    float* o2 = g_f2   + (size_t)pt*CC;
    float* ob = g_base + (size_t)pt*CC;

#pragma unroll 1
    for (int c0 = 0; c0 < CC; c0 += 4) {
        float a1[4], a2[4], a3[4], ap[4];
#pragma unroll
        for (int q = 0; q < 4; q++) {
            a1[q]=sb1[c0+q]; a2[q]=sb2[c0+q]; a3[q]=sb3[c0+q]; ap[q]=sbias2[c0+q];
        }
#pragma unroll
        for (int i4 = 0; i4 < 16; i4++) {
            float x0=fv[4*i4], x1=fv[4*i4+1], x2=fv[4*i4+2], x3=fv[4*i4+3];
#pragma unroll
            for (int q = 0; q < 4; q++) {
                float4 wa = sw1_4[(c0+q)*16 + i4];
                a1[q] += wa.x*x0 + wa.y*x1 + wa.z*x2 + wa.w*x3;
                float4 wb = sw2_4[(c0+q)*16 + i4];
                a2[q] += wb.x*x0 + wb.y*x1 + wb.z*x2 + wb.w*x3;
                float4 wc = sw3_4[(c0+q)*16 + i4];
                a3[q] += wc.x*x0 + wc.y*x1 + wc.z*x2 + wc.w*x3;
            }
        }
#pragma unroll
        for (int j4 = 0; j4 < 8; j4++) {
            float x0=h[4*j4], x1=h[4*j4+1], x2=h[4*j4+2], x3=h[4*j4+3];
#pragma unroll
            for (int q = 0; q < 4; q++) {
                float4 wp = sdw2_4[(c0+q)*8 + j4];
                ap[q] += wp.x*x0 + wp.y*x1 + wp.z*x2 + wp.w*x3;
            }
        }
        float bbv[4];
#pragma unroll
        for (int q = 0; q < 4; q++) {
            float fo = fb[(size_t)(c0+q)*NN];
            bbv[q] = fo + ap[q] + sscA[c0+q]*(a2[q]+a3[q]) + sshA[c0+q];
        }
        *(float4*)(o1+c0) = make_float4(a1[0],a1[1],a1[2],a1[3]);
        *(float4*)(o2+c0) = make_float4(a2[0],a2[1],a2[2],a2[3]);
        *(float4*)(ob+c0) = make_float4(bbv[0],bbv[1],bbv[2],bbv[3]);
    }
}

// ---------------------------------------------------------------------------
// Kernel 2: 32 points / block (1024 thr).
//  Phase A: warp=point, lane=channel-pair -> KNN edge max of f1,f2; x = base + scaleA*(e1+e2)
//  Phase B: warp=j-group(4), lane=point  -> h2 = gelu(bnM(mw1 @ x))
//  Phase C: warp=channel-pair, lane=point -> out = x + mw2 @ h2 (coalesced BCN write)
// ---------------------------------------------------------------------------
__global__ __launch_bounds__(1024) void k2(P2 p) {
    extern __shared__ float sm[];
    float* smw1 = sm;               // 8192  (HID x C)
    float* smw2 = smw1 + 8192;      // 8192  (C x HID)
    float* sxs  = smw2 + 8192;      // 32*65 = 2080  (pitch 65, conflict-free)
    float* sh2  = sxs  + 2080;      // 32*129 = 4128 (pitch 129)
    float* sscM = sh2  + 4128;      // 128
    float* sshM = sscM + 128;       // 128

    const int tid = threadIdx.x;
    for (int i = tid; i < 8192; i += 1024) { smw1[i]=p.mw1[i]; smw2[i]=p.mw2[i]; }
    if (tid < HID) {
        float sc = p.mg[tid]*rsqrtf(p.mv[tid]+BN_EPS);
        sscM[tid]=sc; sshM[tid]=p.mb[tid]-p.mm[tid]*sc;
    }

    const int w = tid >> 5, l = tid & 31;
    const int p0 = blockIdx.x*32;
    const int b  = p0 >> 14;
    const int n0 = p0 & (NN-1);

    // ---- Phase A ----
    {
        const int pt = p0 + w;
        const float2 c1 = ((const float2*)(g_f1 + (size_t)pt*CC))[l];
        const float2 c2 = ((const float2*)(g_f2 + (size_t)pt*CC))[l];
        int jreg = 0;
        if (l < KK) jreg = p.qidx[(size_t)pt*KK + l];
        float m1x=-INFINITY, m1y=-INFINITY, m2x=-INFINITY, m2y=-INFINITY;
        const size_t brow = (size_t)b*NN;
#pragma unroll
        for (int k = 0; k < KK; k++) {
            int j = __shfl_sync(0xffffffffu, jreg, k);
            float2 v1 = ((const float2*)(g_f1 + (brow + (size_t)j)*CC))[l];
            float2 v2 = ((const float2*)(g_f2 + (brow + (size_t)j)*CC))[l];
            m1x=fmaxf(m1x,v1.x); m1y=fmaxf(m1y,v1.y);
            m2x=fmaxf(m2x,v2.x); m2y=fmaxf(m2y,v2.y);
        }
        float e0 = (m1x - c1.x) + (m2x - c2.x);
        float e1 = (m1y - c1.y) + (m2y - c2.y);
        float2 bs = ((const float2*)(g_base + (size_t)pt*CC))[l];
        float sc0 = p.agg_g[2*l  ]*rsqrtf(p.agg_v[2*l  ]+BN_EPS);
        float sc1 = p.agg_g[2*l+1]*rsqrtf(p.agg_v[2*l+1]+BN_EPS);
        sxs[w*65 + 2*l  ] = bs.x + sc0*e0;
        sxs[w*65 + 2*l+1] = bs.y + sc1*e1;
    }
    __syncthreads();

    // ---- Phase B: h2[j] for j in {4w..4w+3}, point = lane ----
    {
        float acc[4] = {0.f,0.f,0.f,0.f};
        const float4* w4 = (const float4*)smw1;
#pragma unroll
        for (int c4 = 0; c4 < 16; c4++) {
            float xa = sxs[l*65 + 4*c4    ];
            float xb = sxs[l*65 + 4*c4 + 1];
            float xc = sxs[l*65 + 4*c4 + 2];
            float xd = sxs[l*65 + 4*c4 + 3];
#pragma unroll
            for (int q = 0; q < 4; q++) {
                float4 wv = w4[(4*w+q)*16 + c4];
                acc[q] += wv.x*xa + wv.y*xb + wv.z*xc + wv.w*xd;
            }
        }
#pragma unroll
        for (int q = 0; q < 4; q++) {
            int j = 4*w + q;
            float y = acc[q]*sscM[j] + sshM[j];
            sh2[l*129 + j] = y * normcdff(y);
        }
    }
    __syncthreads();

    // ---- Phase C: out channels {2w, 2w+1}, point = lane ----
    {
        const int c0 = 2*w, c1c = 2*w+1;
        float acc0 = 0.f, acc1 = 0.f;
        const float4* w4 = (const float4*)smw2;
#pragma unroll
        for (int j4 = 0; j4 < 32; j4++) {
            float xa = sh2[l*129 + 4*j4    ];
            float xb = sh2[l*129 + 4*j4 + 1];
            float xc = sh2[l*129 + 4*j4 + 2];
            float xd = sh2[l*129 + 4*j4 + 3];
            float4 w0 = w4[c0 *32 + j4];
            acc0 += w0.x*xa + w0.y*xb + w0.z*xc + w0.w*xd;
            float4 w1v = w4[c1c*32 + j4];
            acc1 += w1v.x*xa + w1v.y*xb + w1v.z*xc + w1v.w*xd;
        }
        float x0 = sxs[l*65 + c0];
        float x1 = sxs[l*65 + c1c];
        const size_t ob = (size_t)b*CC*NN;
        p.out[ob + (size_t)c0 *NN + n0 + l] = x0 + acc0;
        p.out[ob + (size_t)c1c*NN + n0 + l] = x1 + acc1;
    }
}

// ---------------------------------------------------------------------------
extern "C" void kernel_launch(void* const* d_in, const int* in_sizes, int n_in,
                              void* d_out, int out_size) {
    const float* f        = (const float*)d_in[0];
    const float* dp       = (const float*)d_in[1];
    const int*   qidx     = (const int*)  d_in[2];
    const float* dirv     = (const float*)d_in[3];
    const float* de_w1    = (const float*)d_in[4];
    const float* de_g1    = (const float*)d_in[5];
    const float* de_b1    = (const float*)d_in[6];
    const float* de_m1    = (const float*)d_in[7];
    const float* de_v1    = (const float*)d_in[8];
    const float* de_w2    = (const float*)d_in[9];
    const float* de_bias2 = (const float*)d_in[10];
    const float* w1       = (const float*)d_in[11];
    const float* b1       = (const float*)d_in[12];
    const float* w2       = (const float*)d_in[13];
    const float* b2       = (const float*)d_in[14];
    const float* w3       = (const float*)d_in[15];
    const float* b3       = (const float*)d_in[16];
    const float* agg_g    = (const float*)d_in[17];
    const float* agg_b    = (const float*)d_in[18];
    const float* agg_m    = (const float*)d_in[19];
    const float* agg_v    = (const float*)d_in[20];
    const float* mw1      = (const float*)d_in[21];
    const float* mg       = (const float*)d_in[22];
    const float* mb       = (const float*)d_in[23];
    const float* mm       = (const float*)d_in[24];
    const float* mv       = (const float*)d_in[25];
    const float* mw2      = (const float*)d_in[26];

    P1 p1;
    p1.f=f; p1.dp=dp; p1.dirv=dirv;
    p1.de_w1=de_w1; p1.de_g1=de_g1; p1.de_b1=de_b1; p1.de_m1=de_m1; p1.de_v1=de_v1;
    p1.de_w2=de_w2; p1.de_bias2=de_bias2;
    p1.w1=w1; p1.b1=b1; p1.w2=w2; p1.b2=b2; p1.w3=w3; p1.b3=b3;
    p1.agg_g=agg_g; p1.agg_b=agg_b; p1.agg_m=agg_m; p1.agg_v=agg_v;

    P2 p2;
    p2.qidx=qidx; p2.agg_g=agg_g; p2.agg_v=agg_v;
    p2.mw1=mw1; p2.mg=mg; p2.mb=mb; p2.mm=mm; p2.mv=mv; p2.mw2=mw2;
    p2.out=(float*)d_out;

    const size_t smem1 = 15904 * sizeof(float);   // 63616 B
    const size_t smem2 = 22848 * sizeof(float);   // 91392 B
    cudaFuncSetAttribute(k1, cudaFuncAttributeMaxDynamicSharedMemorySize, (int)smem1);
    cudaFuncSetAttribute(k2, cudaFuncAttributeMaxDynamicSharedMemorySize, (int)smem2);

    k1<<<NPTS/256, 256, smem1>>>(p1);
    k2<<<NPTS/32, 1024, smem2>>>(p2);
}

// round 2
// speedup vs baseline: 1.0015x; 1.0015x over previous
#include <cuda_runtime.h>
#include <math.h>

// Problem constants
#define BB   8
#define NN   16384
#define KK   16
#define CC   64
#define MM   32
#define HH   32
#define HID  128
#define NPTS (BB*NN)          // 131072
#define BN_EPS 1e-5f

// Scratch (point-major layouts: [pt][C])
__device__ float g_f1[(size_t)NPTS*CC];
__device__ float g_f2[(size_t)NPTS*CC];
__device__ float g_base[(size_t)NPTS*CC];

struct P1 {
    const float *f, *dp, *dirv;
    const float *de_w1, *de_g1, *de_b1, *de_m1, *de_v1, *de_w2, *de_bias2;
    const float *w1, *b1, *w2, *b2, *w3, *b3;
    const float *agg_g, *agg_b, *agg_m, *agg_v;
};

struct P2 {
    const int*   qidx;
    const float *agg_g, *agg_v;
    const float *mw1, *mg, *mb, *mm, *mv, *mw2;
    float* out;
};

// ---------------------------------------------------------------------------
// Kernel 1: thread-per-point.
//   theta_max -> DE mlp (pe), f1/f2/f3 = W*f+b, write f1,f2 point-major and
//   base = f + pe + scaleA*(f2+f3) + shiftA   (BN folded affine)
// ---------------------------------------------------------------------------
__global__ __launch_bounds__(256) void k1(P1 p) {
    extern __shared__ float sm[];
    float* sw1   = sm;              // 4096
    float* sw2   = sw1  + 4096;     // 4096
    float* sw3   = sw2  + 4096;     // 4096
    float* sdw1  = sw3  + 4096;     // 1024  (H x M)
    float* sdw2  = sdw1 + 1024;     // 2048  (C x H)
    float* sv0   = sdw2 + 2048;     // 32
    float* sv1   = sv0  + 32;
    float* sv2   = sv1  + 32;
    float* sb1   = sv2  + 32;       // 64
    float* sb2   = sb1  + 64;
    float* sb3   = sb2  + 64;
    float* sbias2= sb3  + 64;
    float* ssc1  = sbias2 + 64;     // 32
    float* ssh1  = ssc1 + 32;
    float* sscA  = ssh1 + 32;       // 64
    float* sshA  = sscA + 64;

    const int tid = threadIdx.x;
    for (int i = tid; i < 4096; i += 256) { sw1[i]=p.w1[i]; sw2[i]=p.w2[i]; sw3[i]=p.w3[i]; }
    for (int i = tid; i < 1024; i += 256) sdw1[i] = p.de_w1[i];
    for (int i = tid; i < 2048; i += 256) sdw2[i] = p.de_w2[i];
    if (tid < 64) {
        sb1[tid]=p.b1[tid]; sb2[tid]=p.b2[tid]; sb3[tid]=p.b3[tid];
        sbias2[tid]=p.de_bias2[tid];
        float sc = p.agg_g[tid]*rsqrtf(p.agg_v[tid]+BN_EPS);
        sscA[tid]=sc; sshA[tid]=p.agg_b[tid]-p.agg_m[tid]*sc;
    }
    if (tid < 32) {
        float v0=p.dirv[tid*3+0], v1=p.dirv[tid*3+1], v2=p.dirv[tid*3+2];
        float inv = 1.f/fmaxf(sqrtf(v0*v0+v1*v1+v2*v2), 1e-12f);
        sv0[tid]=v0*inv; sv1[tid]=v1*inv; sv2[tid]=v2*inv;
        float sc = p.de_g1[tid]*rsqrtf(p.de_v1[tid]+BN_EPS);
        ssc1[tid]=sc; ssh1[tid]=p.de_b1[tid]-p.de_m1[tid]*sc;
    }
    __syncthreads();

    const int pt = blockIdx.x*256 + tid;
    const int b  = pt >> 14;            // N = 2^14
    const int n  = pt & (NN-1);

    // ---- theta_max over k ----
    float tm[MM];
#pragma unroll
    for (int m = 0; m < MM; m++) tm[m] = -INFINITY;
    const float* dpb = p.dp + (size_t)b*3*NN*KK + (size_t)n*KK;
#pragma unroll 1
    for (int k = 0; k < KK; k++) {
        float x0 = dpb[k];
        float x1 = dpb[(size_t)NN*KK + k];
        float x2 = dpb[(size_t)2*NN*KK + k];
        float inv = 1.f/fmaxf(sqrtf(x0*x0+x1*x1+x2*x2), 1e-12f);
        x0*=inv; x1*=inv; x2*=inv;
#pragma unroll
        for (int m = 0; m < MM; m++) {
            float val = sv0[m]*x0 + sv1[m]*x1 + sv2[m]*x2;
            tm[m] = fmaxf(tm[m], val);
        }
    }

    // ---- h = gelu(bn1(de_w1 @ tm)) ----
    float h[HH];
    const float4* sdw1_4 = (const float4*)sdw1;
#pragma unroll
    for (int j = 0; j < HH; j++) {
        float acc = 0.f;
#pragma unroll
        for (int m4 = 0; m4 < 8; m4++) {
            float4 w = sdw1_4[j*8 + m4];
            acc += w.x*tm[4*m4] + w.y*tm[4*m4+1] + w.z*tm[4*m4+2] + w.w*tm[4*m4+3];
        }
        float y = acc*ssc1[j] + ssh1[j];
        h[j] = y * normcdff(y);           // exact GELU
    }

    // ---- load f row into registers ----
    float fv[CC];
    const float* fb = p.f + (size_t)b*CC*NN + n;
#pragma unroll
    for (int i = 0; i < CC; i++) fv[i] = fb[(size_t)i*NN];

    const float4* sw1_4 = (const float4*)sw1;
    const float4* sw2_4 = (const float4*)sw2;
    const float4* sw3_4 = (const float4*)sw3;
    const float4* sdw2_4= (const float4*)sdw2;

    float* o1 = g_f1   + (size_t)pt*CC;
    float* o2 = g_f2   + (size_t)pt*CC;
    float* ob = g_base + (size_t)pt*CC;

#pragma unroll 1
    for (int c0 = 0; c0 < CC; c0 += 4) {
        float a1[4], a2[4], a3[4], ap[4];
#pragma unroll
        for (int q = 0; q < 4; q++) {
            a1[q]=sb1[c0+q]; a2[q]=sb2[c0+q]; a3[q]=sb3[c0+q]; ap[q]=sbias2[c0+q];
        }
#pragma unroll
        for (int i4 = 0; i4 < 16; i4++) {
            float x0=fv[4*i4], x1=fv[4*i4+1], x2=fv[4*i4+2], x3=fv[4*i4+3];
#pragma unroll
            for (int q = 0; q < 4; q++) {
                float4 wa = sw1_4[(c0+q)*16 + i4];
                a1[q] += wa.x*x0 + wa.y*x1 + wa.z*x2 + wa.w*x3;
                float4 wb = sw2_4[(c0+q)*16 + i4];
                a2[q] += wb.x*x0 + wb.y*x1 + wb.z*x2 + wb.w*x3;
                float4 wc = sw3_4[(c0+q)*16 + i4];
                a3[q] += wc.x*x0 + wc.y*x1 + wc.z*x2 + wc.w*x3;
            }
        }
#pragma unroll
        for (int j4 = 0; j4 < 8; j4++) {
            float x0=h[4*j4], x1=h[4*j4+1], x2=h[4*j4+2], x3=h[4*j4+3];
#pragma unroll
            for (int q = 0; q < 4; q++) {
                float4 wp = sdw2_4[(c0+q)*8 + j4];
                ap[q] += wp.x*x0 + wp.y*x1 + wp.z*x2 + wp.w*x3;
            }
        }
        float bbv[4];
#pragma unroll
        for (int q = 0; q < 4; q++) {
            float fo = fb[(size_t)(c0+q)*NN];
            bbv[q] = fo + ap[q] + sscA[c0+q]*(a2[q]+a3[q]) + sshA[c0+q];
        }
        *(float4*)(o1+c0) = make_float4(a1[0],a1[1],a1[2],a1[3]);
        *(float4*)(o2+c0) = make_float4(a2[0],a2[1],a2[2],a2[3]);
        *(float4*)(ob+c0) = make_float4(bbv[0],bbv[1],bbv[2],bbv[3]);
    }
}

// ---------------------------------------------------------------------------
// Kernel 2: 32 points / block (1024 thr).
//  Phase A: warp=point, lane=channel-pair -> KNN edge max of f1,f2; x = base + scaleA*(e1+e2)
//  Phase B: warp=j-group(4), lane=point  -> h2 = gelu(bnM(mw1 @ x))
//  Phase C: warp=channel-pair, lane=point -> out = x + mw2 @ h2 (coalesced BCN write)
// ---------------------------------------------------------------------------
__global__ __launch_bounds__(1024) void k2(P2 p) {
    extern __shared__ float sm[];
    float* smw1 = sm;               // 8192  (HID x C)
    float* smw2 = smw1 + 8192;      // 8192  (C x HID)
    float* sxs  = smw2 + 8192;      // 32*65 = 2080  (pitch 65, conflict-free)
    float* sh2  = sxs  + 2080;      // 32*129 = 4128 (pitch 129)
    float* sscM = sh2  + 4128;      // 128
    float* sshM = sscM + 128;       // 128

    const int tid = threadIdx.x;
    for (int i = tid; i < 8192; i += 1024) { smw1[i]=p.mw1[i]; smw2[i]=p.mw2[i]; }
    if (tid < HID) {
        float sc = p.mg[tid]*rsqrtf(p.mv[tid]+BN_EPS);
        sscM[tid]=sc; sshM[tid]=p.mb[tid]-p.mm[tid]*sc;
    }

    const int w = tid >> 5, l = tid & 31;
    const int p0 = blockIdx.x*32;
    const int b  = p0 >> 14;
    const int n0 = p0 & (NN-1);

    // ---- Phase A ----
    {
        const int pt = p0 + w;
        const float2 c1 = ((const float2*)(g_f1 + (size_t)pt*CC))[l];
        const float2 c2 = ((const float2*)(g_f2 + (size_t)pt*CC))[l];
        int jreg = 0;
        if (l < KK) jreg = p.qidx[(size_t)pt*KK + l];
        float m1x=-INFINITY, m1y=-INFINITY, m2x=-INFINITY, m2y=-INFINITY;
        const size_t brow = (size_t)b*NN;
#pragma unroll
        for (int k = 0; k < KK; k++) {
            int j = __shfl_sync(0xffffffffu, jreg, k);
            float2 v1 = ((const float2*)(g_f1 + (brow + (size_t)j)*CC))[l];
            float2 v2 = ((const float2*)(g_f2 + (brow + (size_t)j)*CC))[l];
            m1x=fmaxf(m1x,v1.x); m1y=fmaxf(m1y,v1.y);
            m2x=fmaxf(m2x,v2.x); m2y=fmaxf(m2y,v2.y);
        }
        float e0 = (m1x - c1.x) + (m2x - c2.x);
        float e1 = (m1y - c1.y) + (m2y - c2.y);
        float2 bs = ((const float2*)(g_base + (size_t)pt*CC))[l];
        float sc0 = p.agg_g[2*l  ]*rsqrtf(p.agg_v[2*l  ]+BN_EPS);
        float sc1 = p.agg_g[2*l+1]*rsqrtf(p.agg_v[2*l+1]+BN_EPS);
        sxs[w*65 + 2*l  ] = bs.x + sc0*e0;
        sxs[w*65 + 2*l+1] = bs.y + sc1*e1;
    }
    __syncthreads();

    // ---- Phase B: h2[j] for j in {4w..4w+3}, point = lane ----
    {
        float acc[4] = {0.f,0.f,0.f,0.f};
        const float4* w4 = (const float4*)smw1;
#pragma unroll
        for (int c4 = 0; c4 < 16; c4++) {
            float xa = sxs[l*65 + 4*c4    ];
            float xb = sxs[l*65 + 4*c4 + 1];
            float xc = sxs[l*65 + 4*c4 + 2];
            float xd = sxs[l*65 + 4*c4 + 3];
#pragma unroll
            for (int q = 0; q < 4; q++) {
                float4 wv = w4[(4*w+q)*16 + c4];
                acc[q] += wv.x*xa + wv.y*xb + wv.z*xc + wv.w*xd;
            }
        }
#pragma unroll
        for (int q = 0; q < 4; q++) {
            int j = 4*w + q;
            float y = acc[q]*sscM[j] + sshM[j];
            sh2[l*129 + j] = y * normcdff(y);
        }
    }
    __syncthreads();

    // ---- Phase C: out channels {2w, 2w+1}, point = lane ----
    {
        const int c0 = 2*w, c1c = 2*w+1;
        float acc0 = 0.f, acc1 = 0.f;
        const float4* w4 = (const float4*)smw2;
#pragma unroll
        for (int j4 = 0; j4 < 32; j4++) {
            float xa = sh2[l*129 + 4*j4    ];
            float xb = sh2[l*129 + 4*j4 + 1];
            float xc = sh2[l*129 + 4*j4 + 2];
            float xd = sh2[l*129 + 4*j4 + 3];
            float4 w0 = w4[c0 *32 + j4];
            acc0 += w0.x*xa + w0.y*xb + w0.z*xc + w0.w*xd;
            float4 w1v = w4[c1c*32 + j4];
            acc1 += w1v.x*xa + w1v.y*xb + w1v.z*xc + w1v.w*xd;
        }
        float x0 = sxs[l*65 + c0];
        float x1 = sxs[l*65 + c1c];
        const size_t ob = (size_t)b*CC*NN;
        p.out[ob + (size_t)c0 *NN + n0 + l] = x0 + acc0;
        p.out[ob + (size_t)c1c*NN + n0 + l] = x1 + acc1;
    }
}

// ---------------------------------------------------------------------------
extern "C" void kernel_launch(void* const* d_in, const int* in_sizes, int n_in,
                              void* d_out, int out_size) {
    const float* f        = (const float*)d_in[0];
    const float* dp       = (const float*)d_in[1];
    const int*   qidx     = (const int*)  d_in[2];
    const float* dirv     = (const float*)d_in[3];
    const float* de_w1    = (const float*)d_in[4];
    const float* de_g1    = (const float*)d_in[5];
    const float* de_b1    = (const float*)d_in[6];
    const float* de_m1    = (const float*)d_in[7];
    const float* de_v1    = (const float*)d_in[8];
    const float* de_w2    = (const float*)d_in[9];
    const float* de_bias2 = (const float*)d_in[10];
    const float* w1       = (const float*)d_in[11];
    const float* b1       = (const float*)d_in[12];
    const float* w2       = (const float*)d_in[13];
    const float* b2       = (const float*)d_in[14];
    const float* w3       = (const float*)d_in[15];
    const float* b3       = (const float*)d_in[16];
    const float* agg_g    = (const float*)d_in[17];
    const float* agg_b    = (const float*)d_in[18];
    const float* agg_m    = (const float*)d_in[19];
    const float* agg_v    = (const float*)d_in[20];
    const float* mw1      = (const float*)d_in[21];
    const float* mg       = (const float*)d_in[22];
    const float* mb       = (const float*)d_in[23];
    const float* mm       = (const float*)d_in[24];
    const float* mv       = (const float*)d_in[25];
    const float* mw2      = (const float*)d_in[26];

    P1 p1;
    p1.f=f; p1.dp=dp; p1.dirv=dirv;
    p1.de_w1=de_w1; p1.de_g1=de_g1; p1.de_b1=de_b1; p1.de_m1=de_m1; p1.de_v1=de_v1;
    p1.de_w2=de_w2; p1.de_bias2=de_bias2;
    p1.w1=w1; p1.b1=b1; p1.w2=w2; p1.b2=b2; p1.w3=w3; p1.b3=b3;
    p1.agg_g=agg_g; p1.agg_b=agg_b; p1.agg_m=agg_m; p1.agg_v=agg_v;

    P2 p2;
    p2.qidx=qidx; p2.agg_g=agg_g; p2.agg_v=agg_v;
    p2.mw1=mw1; p2.mg=mg; p2.mb=mb; p2.mm=mm; p2.mv=mv; p2.mw2=mw2;
    p2.out=(float*)d_out;

    const size_t smem1 = 15904 * sizeof(float);   // 63616 B
    const size_t smem2 = 22848 * sizeof(float);   // 91392 B
    cudaFuncSetAttribute(k1, cudaFuncAttributeMaxDynamicSharedMemorySize, (int)smem1);
    cudaFuncSetAttribute(k2, cudaFuncAttributeMaxDynamicSharedMemorySize, (int)smem2);

    k1<<<NPTS/256, 256, smem1>>>(p1);
    k2<<<NPTS/32, 1024, smem2>>>(p2);
}

// round 3
// speedup vs baseline: 1.1648x; 1.1630x over previous
#include <cuda_runtime.h>
#include <math.h>

// Problem constants
#define BB   8
#define NN   16384
#define KK   16
#define CC   64
#define MM   32
#define HH   32
#define HID  128
#define NPTS (BB*NN)          // 131072
#define BN_EPS 1e-5f

// Scratch (point-major layouts: [pt][C])
__device__ float g_f1[(size_t)NPTS*CC];
__device__ float g_f2[(size_t)NPTS*CC];
__device__ float g_base[(size_t)NPTS*CC];

struct P1 {
    const float *f, *dp, *dirv;
    const float *de_w1, *de_g1, *de_b1, *de_m1, *de_v1, *de_w2, *de_bias2;
    const float *w1, *b1, *w2, *b2, *w3, *b3;
    const float *agg_g, *agg_b, *agg_m, *agg_v;
};

struct P2 {
    const int*   qidx;
    const float *agg_g, *agg_v;
    const float *mw1, *mg, *mb, *mm, *mv, *mw2;
    float* out;
};

// ---------------------------------------------------------------------------
// Kernel 1: thread-per-point.
//   theta_max -> DE mlp (pe), f1/f2 = W*f+b, write f1,f2 point-major and
//   base = f + pe + scaleA*(f2+f3) + shiftA   (BN folded affine)
// ---------------------------------------------------------------------------
__global__ __launch_bounds__(256, 2) void k1(P1 p) {
    extern __shared__ float sm[];
    float* sw1   = sm;              // 4096
    float* sw2   = sw1  + 4096;     // 4096
    float* sw3   = sw2  + 4096;     // 4096
    float* sdw1  = sw3  + 4096;     // 1024  (H x M)
    float* sdw2  = sdw1 + 1024;     // 2048  (C x H)
    float* svv   = sdw2 + 2048;     // 128   (M x 4, float4 aligned)
    float* sb1   = svv  + 128;      // 64
    float* sb2   = sb1  + 64;
    float* sb3   = sb2  + 64;
    float* sbias2= sb3  + 64;
    float* ssc1  = sbias2 + 64;     // 32
    float* ssh1  = ssc1 + 32;
    float* sscA  = ssh1 + 32;       // 64
    float* sshA  = sscA + 64;       // 64  -> total 15936 floats

    const int tid = threadIdx.x;
    for (int i = tid; i < 4096; i += 256) { sw1[i]=p.w1[i]; sw2[i]=p.w2[i]; sw3[i]=p.w3[i]; }
    for (int i = tid; i < 1024; i += 256) sdw1[i] = p.de_w1[i];
    for (int i = tid; i < 2048; i += 256) sdw2[i] = p.de_w2[i];
    if (tid < 64) {
        sb1[tid]=p.b1[tid]; sb2[tid]=p.b2[tid]; sb3[tid]=p.b3[tid];
        sbias2[tid]=p.de_bias2[tid];
        float sc = p.agg_g[tid]*rsqrtf(p.agg_v[tid]+BN_EPS);
        sscA[tid]=sc; sshA[tid]=p.agg_b[tid]-p.agg_m[tid]*sc;
    }
    if (tid < 32) {
        float v0=p.dirv[tid*3+0], v1=p.dirv[tid*3+1], v2=p.dirv[tid*3+2];
        float inv = rsqrtf(fmaxf(v0*v0+v1*v1+v2*v2, 1e-24f));
        svv[tid*4+0]=v0*inv; svv[tid*4+1]=v1*inv; svv[tid*4+2]=v2*inv; svv[tid*4+3]=0.f;
        float sc = p.de_g1[tid]*rsqrtf(p.de_v1[tid]+BN_EPS);
        ssc1[tid]=sc; ssh1[tid]=p.de_b1[tid]-p.de_m1[tid]*sc;
    }
    __syncthreads();

    const int pt = blockIdx.x*256 + tid;
    const int b  = pt >> 14;            // N = 2^14
    const int n  = pt & (NN-1);

    // ---- load + normalize dp rows (16 neighbors x 3 dims) ----
    float xn0[KK], xn1[KK], xn2[KK];
    const float4* dp4 = (const float4*)(p.dp + (size_t)b*3*NN*KK + (size_t)n*KK);
#pragma unroll
    for (int k4 = 0; k4 < 4; k4++) {
        float4 A = dp4[k4];
        float4 Bv= dp4[(NN*KK/4) + k4];
        float4 Cv= dp4[(2*NN*KK/4) + k4];
        float ax[4]={A.x,A.y,A.z,A.w}, bx[4]={Bv.x,Bv.y,Bv.z,Bv.w}, cx[4]={Cv.x,Cv.y,Cv.z,Cv.w};
#pragma unroll
        for (int kk = 0; kk < 4; kk++) {
            float x0=ax[kk], x1=bx[kk], x2=cx[kk];
            float inv = rsqrtf(fmaxf(x0*x0+x1*x1+x2*x2, 1e-24f));
            xn0[4*k4+kk]=x0*inv; xn1[4*k4+kk]=x1*inv; xn2[4*k4+kk]=x2*inv;
        }
    }

    // ---- theta_max: m outer (one float4 broadcast LDS per m) ----
    float tm[MM];
    const float4* sv4 = (const float4*)svv;
#pragma unroll
    for (int m = 0; m < MM; m++) {
        float4 v = sv4[m];
        float acc = -INFINITY;
#pragma unroll
        for (int k = 0; k < KK; k++)
            acc = fmaxf(acc, v.x*xn0[k] + v.y*xn1[k] + v.z*xn2[k]);
        tm[m] = acc;
    }

    // ---- h = gelu(bn1(de_w1 @ tm)) ----
    float h[HH];
    const float4* sdw1_4 = (const float4*)sdw1;
#pragma unroll
    for (int j = 0; j < HH; j++) {
        float acc = 0.f;
#pragma unroll
        for (int m4 = 0; m4 < 8; m4++) {
            float4 w = sdw1_4[j*8 + m4];
            acc += w.x*tm[4*m4] + w.y*tm[4*m4+1] + w.z*tm[4*m4+2] + w.w*tm[4*m4+3];
        }
        float y = acc*ssc1[j] + ssh1[j];
        h[j] = y * normcdff(y);           // exact GELU
    }

    // ---- load f row into registers (coalesced across lanes) ----
    float fv[CC];
    const float* fb = p.f + (size_t)b*CC*NN + n;
#pragma unroll
    for (int i = 0; i < CC; i++) fv[i] = fb[(size_t)i*NN];

    const float4* sw1_4 = (const float4*)sw1;
    const float4* sw2_4 = (const float4*)sw2;
    const float4* sw3_4 = (const float4*)sw3;
    const float4* sdw2_4= (const float4*)sdw2;

    float* o1 = g_f1   + (size_t)pt*CC;
    float* o2 = g_f2   + (size_t)pt*CC;
    float* ob = g_base + (size_t)pt*CC;

#pragma unroll 1
    for (int c0 = 0; c0 < CC; c0 += 4) {
        float a1[4], a2[4], a3[4], ap[4];
#pragma unroll
        for (int q = 0; q < 4; q++) {
            a1[q]=sb1[c0+q]; a2[q]=sb2[c0+q]; a3[q]=sb3[c0+q]; ap[q]=sbias2[c0+q];
        }
#pragma unroll
        for (int i4 = 0; i4 < 16; i4++) {
            float x0=fv[4*i4], x1=fv[4*i4+1], x2=fv[4*i4+2], x3=fv[4*i4+3];
#pragma unroll
            for (int q = 0; q < 4; q++) {
                float4 wa = sw1_4[(c0+q)*16 + i4];
                a1[q] += wa.x*x0 + wa.y*x1 + wa.z*x2 + wa.w*x3;
            }
#pragma unroll
            for (int q = 0; q < 4; q++) {
                float4 wb = sw2_4[(c0+q)*16 + i4];
                a2[q] += wb.x*x0 + wb.y*x1 + wb.z*x2 + wb.w*x3;
            }
#pragma unroll
            for (int q = 0; q < 4; q++) {
                float4 wc = sw3_4[(c0+q)*16 + i4];
                a3[q] += wc.x*x0 + wc.y*x1 + wc.z*x2 + wc.w*x3;
            }
        }
#pragma unroll
        for (int j4 = 0; j4 < 8; j4++) {
            float x0=h[4*j4], x1=h[4*j4+1], x2=h[4*j4+2], x3=h[4*j4+3];
#pragma unroll
            for (int q = 0; q < 4; q++) {
                float4 wp = sdw2_4[(c0+q)*8 + j4];
                ap[q] += wp.x*x0 + wp.y*x1 + wp.z*x2 + wp.w*x3;
            }
        }
        float bbv[4];
#pragma unroll
        for (int q = 0; q < 4; q++) {
            bbv[q] = fv[c0+q] + ap[q] + sscA[c0+q]*(a2[q]+a3[q]) + sshA[c0+q];
        }
        *(float4*)(o1+c0) = make_float4(a1[0],a1[1],a1[2],a1[3]);
        *(float4*)(o2+c0) = make_float4(a2[0],a2[1],a2[2],a2[3]);
        *(float4*)(ob+c0) = make_float4(bbv[0],bbv[1],bbv[2],bbv[3]);
    }
}

// ---------------------------------------------------------------------------
// Kernel 2: 64 points / block, 512 threads, 2 blocks/SM.
//  Phase A: warp = 4 points, lane = channel-pair -> gather-max; x -> sxs
//  Phase B: warp = 8 j's, lane = point (2 passes) -> h2 = gelu(bnM(mw1 @ x))
//  Phase C: warp = 4 channels, lane = point (2 passes) -> out = x + mw2 @ h2
//  Weight smem buffer reused: mw1 first, reloaded with mw2 after phase B.
// ---------------------------------------------------------------------------
#define PITCH_X 68      // 64 pts x 68 floats (17 float4), Δbank=4 per octet
#define PITCH_H 132     // 64 pts x 132 floats (33 float4)

__global__ __launch_bounds__(512, 2) void k2(P2 p) {
    extern __shared__ float sm[];
    float* sw   = sm;               // 8192 (mw1, then mw2)
    float* sxs  = sw   + 8192;      // 64*68 = 4352
    float* sh2  = sxs  + 4352;      // 64*132 = 8448
    float* sscM = sh2  + 8448;      // 128
    float* sshM = sscM + 128;       // 128  -> total 21248 floats (84992 B)

    const int tid = threadIdx.x;
    const int w = tid >> 5, l = tid & 31;

    // load mw1 (float4, coalesced)
    {
        const float4* src = (const float4*)p.mw1;
        float4* dst = (float4*)sw;
        for (int i = tid; i < 2048; i += 512) dst[i] = src[i];
    }
    if (tid < HID) {
        float sc = p.mg[tid]*rsqrtf(p.mv[tid]+BN_EPS);
        sscM[tid]=sc; sshM[tid]=p.mb[tid]-p.mm[tid]*sc;
    }

    const int p0 = blockIdx.x*64;
    const int b  = p0 >> 14;
    const int n0 = p0 & (NN-1);

    // ---- Phase A: gather + edge max; each warp does 4 points ----
    {
        const float sc0 = p.agg_g[2*l  ]*rsqrtf(p.agg_v[2*l  ]+BN_EPS);
        const float sc1 = p.agg_g[2*l+1]*rsqrtf(p.agg_v[2*l+1]+BN_EPS);
        const size_t brow = (size_t)b*NN;
#pragma unroll 1
        for (int i = 0; i < 4; i++) {
            const int lp = w*4 + i;
            const int pt = p0 + lp;
            const float2 c1 = ((const float2*)(g_f1 + (size_t)pt*CC))[l];
            const float2 c2 = ((const float2*)(g_f2 + (size_t)pt*CC))[l];
            int jreg = 0;
            if (l < KK) jreg = p.qidx[(size_t)pt*KK + l];
            float m1x=-INFINITY, m1y=-INFINITY, m2x=-INFINITY, m2y=-INFINITY;
#pragma unroll
            for (int k = 0; k < KK; k++) {
                int j = __shfl_sync(0xffffffffu, jreg, k);
                float2 v1 = ((const float2*)(g_f1 + (brow + (size_t)j)*CC))[l];
                float2 v2 = ((const float2*)(g_f2 + (brow + (size_t)j)*CC))[l];
                m1x=fmaxf(m1x,v1.x); m1y=fmaxf(m1y,v1.y);
                m2x=fmaxf(m2x,v2.x); m2y=fmaxf(m2y,v2.y);
            }
            float e0 = (m1x - c1.x) + (m2x - c2.x);
            float e1 = (m1y - c1.y) + (m2y - c2.y);
            float2 bs = ((const float2*)(g_base + (size_t)pt*CC))[l];
            sxs[lp*PITCH_X + 2*l  ] = bs.x + sc0*e0;
            sxs[lp*PITCH_X + 2*l+1] = bs.y + sc1*e1;
        }
    }
    __syncthreads();

    // ---- Phase B: h2 = gelu(bnM(mw1 @ x)); warp -> 8 j's, 2 point passes ----
    {
        const float4* w4 = (const float4*)sw;
        const float4* x4 = (const float4*)sxs;    // pitch 17 float4
        const int jg = w*8;
        float acc0[8], acc1[8];
#pragma unroll
        for (int q = 0; q < 8; q++) { acc0[q]=0.f; acc1[q]=0.f; }
#pragma unroll
        for (int c4 = 0; c4 < 16; c4++) {
            float4 xa = x4[l*17 + c4];
            float4 xb = x4[(32+l)*17 + c4];
#pragma unroll
            for (int q = 0; q < 8; q++) {
                float4 wv = w4[(jg+q)*16 + c4];
                acc0[q] += wv.x*xa.x + wv.y*xa.y + wv.z*xa.z + wv.w*xa.w;
                acc1[q] += wv.x*xb.x + wv.y*xb.y + wv.z*xb.z + wv.w*xb.w;
            }
        }
        float h0[8], h1[8];
#pragma unroll
        for (int q = 0; q < 8; q++) {
            float sc = sscM[jg+q], sh = sshM[jg+q];
            float y0 = acc0[q]*sc + sh;
            float y1 = acc1[q]*sc + sh;
            h0[q] = y0 * normcdff(y0);
            h1[q] = y1 * normcdff(y1);
        }
        float4* h4 = (float4*)sh2;                // pitch 33 float4
        h4[l*33      + (jg>>2)    ] = make_float4(h0[0],h0[1],h0[2],h0[3]);
        h4[l*33      + (jg>>2) + 1] = make_float4(h0[4],h0[5],h0[6],h0[7]);
        h4[(32+l)*33 + (jg>>2)    ] = make_float4(h1[0],h1[1],h1[2],h1[3]);
        h4[(32+l)*33 + (jg>>2) + 1] = make_float4(h1[4],h1[5],h1[6],h1[7]);
    }
    __syncthreads();

    // reload weight buffer with mw2
    {
        const float4* src = (const float4*)p.mw2;
        float4* dst = (float4*)sw;
        for (int i = tid; i < 2048; i += 512) dst[i] = src[i];
    }
    __syncthreads();

    // ---- Phase C: out = x + mw2 @ h2; warp -> 4 channels, 2 point passes ----
    {
        const float4* w4 = (const float4*)sw;
        const float4* h4 = (const float4*)sh2;
        const int cg = w*4;
        float acc0[4] = {0.f,0.f,0.f,0.f};
        float acc1[4] = {0.f,0.f,0.f,0.f};
#pragma unroll
        for (int j4 = 0; j4 < 32; j4++) {
            float4 ha = h4[l*33 + j4];
            float4 hb = h4[(32+l)*33 + j4];
#pragma unroll
            for (int q = 0; q < 4; q++) {
                float4 wv = w4[(cg+q)*32 + j4];
                acc0[q] += wv.x*ha.x + wv.y*ha.y + wv.z*ha.z + wv.w*ha.w;
                acc1[q] += wv.x*hb.x + wv.y*hb.y + wv.z*hb.z + wv.w*hb.w;
            }
        }
        const size_t ob = (size_t)b*CC*NN;
#pragma unroll
        for (int q = 0; q < 4; q++) {
            int ch = cg + q;
            float x0 = sxs[l*PITCH_X + ch];
            float x1 = sxs[(32+l)*PITCH_X + ch];
            p.out[ob + (size_t)ch*NN + n0 + l     ] = x0 + acc0[q];
            p.out[ob + (size_t)ch*NN + n0 + 32 + l] = x1 + acc1[q];
        }
    }
}

// ---------------------------------------------------------------------------
extern "C" void kernel_launch(void* const* d_in, const int* in_sizes, int n_in,
                              void* d_out, int out_size) {
    const float* f        = (const float*)d_in[0];
    const float* dp       = (const float*)d_in[1];
    const int*   qidx     = (const int*)  d_in[2];
    const float* dirv     = (const float*)d_in[3];
    const float* de_w1    = (const float*)d_in[4];
    const float* de_g1    = (const float*)d_in[5];
    const float* de_b1    = (const float*)d_in[6];
    const float* de_m1    = (const float*)d_in[7];
    const float* de_v1    = (const float*)d_in[8];
    const float* de_w2    = (const float*)d_in[9];
    const float* de_bias2 = (const float*)d_in[10];
    const float* w1       = (const float*)d_in[11];
    const float* b1       = (const float*)d_in[12];
    const float* w2       = (const float*)d_in[13];
    const float* b2       = (const float*)d_in[14];
    const float* w3       = (const float*)d_in[15];
    const float* b3       = (const float*)d_in[16];
    const float* agg_g    = (const float*)d_in[17];
    const float* agg_b    = (const float*)d_in[18];
    const float* agg_m    = (const float*)d_in[19];
    const float* agg_v    = (const float*)d_in[20];
    const float* mw1      = (const float*)d_in[21];
    const float* mg       = (const float*)d_in[22];
    const float* mb       = (const float*)d_in[23];
    const float* mm       = (const float*)d_in[24];
    const float* mv       = (const float*)d_in[25];
    const float* mw2      = (const float*)d_in[26];

    P1 p1;
    p1.f=f; p1.dp=dp; p1.dirv=dirv;
    p1.de_w1=de_w1; p1.de_g1=de_g1; p1.de_b1=de_b1; p1.de_m1=de_m1; p1.de_v1=de_v1;
    p1.de_w2=de_w2; p1.de_bias2=de_bias2;
    p1.w1=w1; p1.b1=b1; p1.w2=w2; p1.b2=b2; p1.w3=w3; p1.b3=b3;
    p1.agg_g=agg_g; p1.agg_b=agg_b; p1.agg_m=agg_m; p1.agg_v=agg_v;

    P2 p2;
    p2.qidx=qidx; p2.agg_g=agg_g; p2.agg_v=agg_v;
    p2.mw1=mw1; p2.mg=mg; p2.mb=mb; p2.mm=mm; p2.mv=mv; p2.mw2=mw2;
    p2.out=(float*)d_out;

    const size_t smem1 = 15936 * sizeof(float);   // 63744 B
    const size_t smem2 = 21248 * sizeof(float);   // 84992 B
    cudaFuncSetAttribute(k1, cudaFuncAttributeMaxDynamicSharedMemorySize, (int)smem1);
    cudaFuncSetAttribute(k2, cudaFuncAttributeMaxDynamicSharedMemorySize, (int)smem2);

    k1<<<NPTS/256, 256, smem1>>>(p1);
    k2<<<NPTS/64, 512, smem2>>>(p2);
}

// round 4
// speedup vs baseline: 1.1912x; 1.0226x over previous
#include <cuda_runtime.h>
#include <cuda_fp16.h>
#include <math.h>

// Problem constants
#define BB   8
#define NN   16384
#define KK   16
#define CC   64
#define MM   32
#define HH   32
#define HID  128
#define NPTS (BB*NN)          // 131072
#define BN_EPS 1e-5f

typedef unsigned long long u64;

// Packed fp32x2 FMA (Blackwell FFMA2) — only reachable via PTX fma.rn.f32x2
#define FFMA2(d,a,b,c) asm("fma.rn.f32x2 %0, %1, %2, %3;" : "=l"(d) : "l"(a), "l"(b), "l"(c))
#define PACK2(d,lo,hi) asm("mov.b64 %0, {%1, %2};" : "=l"(d) : "f"(lo), "f"(hi))
#define UNPK2(lo,hi,d) asm("mov.b64 {%0, %1}, %2;" : "=f"(lo), "=f"(hi) : "l"(d))

union F4 { float4 v; u64 p[2]; };

// Scratch: f1|f2 interleaved fp16 rows (256B/point), base fp32 point-major
__device__ __half g_f12[(size_t)NPTS*128];
__device__ float  g_base[(size_t)NPTS*CC];

struct P1 {
    const float *f, *dp, *dirv;
    const float *de_w1, *de_g1, *de_b1, *de_m1, *de_v1, *de_w2, *de_bias2;
    const float *w1, *b1, *w2, *b2, *w3, *b3;
    const float *agg_g, *agg_b, *agg_m, *agg_v;
};

struct P2 {
    const int*   qidx;
    const float *agg_g, *agg_v;
    const float *mw1, *mg, *mb, *mm, *mv, *mw2;
    float* out;
};

// ---------------------------------------------------------------------------
// Kernel 1: thread-per-point.  theta_max -> DE mlp -> f1/f2/f3 (FFMA2),
// writes f1,f2 as fp16 rows + base fp32.
// ---------------------------------------------------------------------------
__global__ __launch_bounds__(256) void k1(P1 p) {
    extern __shared__ float sm[];
    float* swt1  = sm;              // 64*68 = 4352  transposed w1 [i][c]
    float* swt2  = swt1 + 4352;
    float* swt3  = swt2 + 4352;
    float* sdw2t = swt3 + 4352;     // 32*68 = 2176  transposed de_w2 [j][c]
    float* sdw1  = sdw2t + 2176;    // 1024  (H x M row-major)
    float* svv   = sdw1 + 1024;     // 128   (M x float4)
    float* sb1   = svv  + 128;      // 64
    float* sb2   = sb1  + 64;
    float* sb3   = sb2  + 64;
    float* sbias2= sb3  + 64;
    float* ssc1  = sbias2 + 64;     // 32
    float* ssh1  = ssc1 + 32;
    float* sscA  = ssh1 + 32;       // 64
    float* sshA  = sscA + 64;       // -> 16832 floats total

    const int tid = threadIdx.x;
    // transposed weight loads (coalesced global read, 8-way smem write conflict ok)
    for (int idx = tid; idx < 4096; idx += 256) {
        int c = idx >> 6, i = idx & 63;
        swt1[i*68+c] = p.w1[idx];
        swt2[i*68+c] = p.w2[idx];
        swt3[i*68+c] = p.w3[idx];
    }
    for (int idx = tid; idx < 2048; idx += 256) {   // de_w2 is [c][j], 64x32
        int c = idx >> 5, j = idx & 31;
        sdw2t[j*68+c] = p.de_w2[idx];
    }
    for (int i = tid; i < 1024; i += 256) sdw1[i] = p.de_w1[i];
    if (tid < 64) {
        sb1[tid]=p.b1[tid]; sb2[tid]=p.b2[tid]; sb3[tid]=p.b3[tid];
        sbias2[tid]=p.de_bias2[tid];
        float sc = p.agg_g[tid]*rsqrtf(p.agg_v[tid]+BN_EPS);
        sscA[tid]=sc; sshA[tid]=p.agg_b[tid]-p.agg_m[tid]*sc;
    }
    if (tid < 32) {
        float v0=p.dirv[tid*3+0], v1=p.dirv[tid*3+1], v2=p.dirv[tid*3+2];
        float inv = rsqrtf(fmaxf(v0*v0+v1*v1+v2*v2, 1e-24f));
        svv[tid*4+0]=v0*inv; svv[tid*4+1]=v1*inv; svv[tid*4+2]=v2*inv; svv[tid*4+3]=0.f;
        float sc = p.de_g1[tid]*rsqrtf(p.de_v1[tid]+BN_EPS);
        ssc1[tid]=sc; ssh1[tid]=p.de_b1[tid]-p.de_m1[tid]*sc;
    }
    __syncthreads();

    const int pt = blockIdx.x*256 + tid;
    const int b  = pt >> 14;
    const int n  = pt & (NN-1);

    // ---- load + normalize dp (16 neighbors x 3 dims) ----
    float xn0[KK], xn1[KK], xn2[KK];
    const float4* dp4 = (const float4*)(p.dp + (size_t)b*3*NN*KK + (size_t)n*KK);
#pragma unroll
    for (int k4 = 0; k4 < 4; k4++) {
        float4 A = dp4[k4];
        float4 Bv= dp4[(NN*KK/4) + k4];
        float4 Cv= dp4[(2*NN*KK/4) + k4];
        float ax[4]={A.x,A.y,A.z,A.w}, bx[4]={Bv.x,Bv.y,Bv.z,Bv.w}, cx[4]={Cv.x,Cv.y,Cv.z,Cv.w};
#pragma unroll
        for (int kk = 0; kk < 4; kk++) {
            float x0=ax[kk], x1=bx[kk], x2=cx[kk];
            float inv = rsqrtf(fmaxf(x0*x0+x1*x1+x2*x2, 1e-24f));
            xn0[4*k4+kk]=x0*inv; xn1[4*k4+kk]=x1*inv; xn2[4*k4+kk]=x2*inv;
        }
    }

    // ---- theta_max (m outer, one float4 broadcast per m) ----
    float tm[MM];
    const float4* sv4 = (const float4*)svv;
#pragma unroll
    for (int m = 0; m < MM; m++) {
        float4 v = sv4[m];
        float acc = -INFINITY;
#pragma unroll
        for (int k = 0; k < KK; k++)
            acc = fmaxf(acc, v.x*xn0[k] + v.y*xn1[k] + v.z*xn2[k]);
        tm[m] = acc;
    }

    // ---- h = gelu(bn1(de_w1 @ tm)) ----
    float h[HH];
    const float4* sdw1_4 = (const float4*)sdw1;
#pragma unroll
    for (int j = 0; j < HH; j++) {
        float acc = 0.f;
#pragma unroll
        for (int m4 = 0; m4 < 8; m4++) {
            float4 w = sdw1_4[j*8 + m4];
            acc += w.x*tm[4*m4] + w.y*tm[4*m4+1] + w.z*tm[4*m4+2] + w.w*tm[4*m4+3];
        }
        float y = acc*ssc1[j] + ssh1[j];
        h[j] = y * normcdff(y);
    }

    // ---- f row into registers (coalesced: stride NN across lanes) ----
    float fv[CC];
    const float* fb = p.f + (size_t)b*CC*NN + n;
#pragma unroll
    for (int i = 0; i < CC; i++) fv[i] = fb[(size_t)i*NN];

    __half* o12 = g_f12 + (size_t)pt*128;
    float*  ob  = g_base + (size_t)pt*CC;

#pragma unroll 1
    for (int c0 = 0; c0 < CC; c0 += 4) {
        u64 a1p0,a1p1,a2p0,a2p1,a3p0,a3p1,app0,app1;
        PACK2(a1p0, sb1[c0], sb1[c0+1]);    PACK2(a1p1, sb1[c0+2], sb1[c0+3]);
        PACK2(a2p0, sb2[c0], sb2[c0+1]);    PACK2(a2p1, sb2[c0+2], sb2[c0+3]);
        PACK2(a3p0, sb3[c0], sb3[c0+1]);    PACK2(a3p1, sb3[c0+2], sb3[c0+3]);
        PACK2(app0, sbias2[c0], sbias2[c0+1]); PACK2(app1, sbias2[c0+2], sbias2[c0+3]);
#pragma unroll
        for (int i = 0; i < CC; i++) {
            u64 xd; PACK2(xd, fv[i], fv[i]);
            F4 wa; wa.v = *(const float4*)&swt1[i*68 + c0];
            FFMA2(a1p0, wa.p[0], xd, a1p0);
            FFMA2(a1p1, wa.p[1], xd, a1p1);
            F4 wb; wb.v = *(const float4*)&swt2[i*68 + c0];
            FFMA2(a2p0, wb.p[0], xd, a2p0);
            FFMA2(a2p1, wb.p[1], xd, a2p1);
            F4 wc; wc.v = *(const float4*)&swt3[i*68 + c0];
            FFMA2(a3p0, wc.p[0], xd, a3p0);
            FFMA2(a3p1, wc.p[1], xd, a3p1);
        }
#pragma unroll
        for (int j = 0; j < HH; j++) {
            u64 hd; PACK2(hd, h[j], h[j]);
            F4 wp; wp.v = *(const float4*)&sdw2t[j*68 + c0];
            FFMA2(app0, wp.p[0], hd, app0);
            FFMA2(app1, wp.p[1], hd, app1);
        }
        float f1a,f1b,f1c,f1d, f2a,f2b,f2c,f2d, f3a,f3b,f3c,f3d, pa,pb,pc,pd;
        UNPK2(f1a,f1b,a1p0); UNPK2(f1c,f1d,a1p1);
        UNPK2(f2a,f2b,a2p0); UNPK2(f2c,f2d,a2p1);
        UNPK2(f3a,f3b,a3p0); UNPK2(f3c,f3d,a3p1);
        UNPK2(pa,pb,app0);   UNPK2(pc,pd,app1);

        *(__half2*)(o12 + c0    )  = __floats2half2_rn(f1a,f1b);
        *(__half2*)(o12 + c0 + 2)  = __floats2half2_rn(f1c,f1d);
        *(__half2*)(o12 + 64+c0  ) = __floats2half2_rn(f2a,f2b);
        *(__half2*)(o12 + 64+c0+2) = __floats2half2_rn(f2c,f2d);

        float b0 = fv[c0  ] + pa + sscA[c0  ]*(f2a+f3a) + sshA[c0  ];
        float b1v= fv[c0+1] + pb + sscA[c0+1]*(f2b+f3b) + sshA[c0+1];
        float b2v= fv[c0+2] + pc + sscA[c0+2]*(f2c+f3c) + sshA[c0+2];
        float b3v= fv[c0+3] + pd + sscA[c0+3]*(f2d+f3d) + sshA[c0+3];
        *(float4*)(ob + c0) = make_float4(b0,b1v,b2v,b3v);
    }
}

// ---------------------------------------------------------------------------
// Kernel 2: 64 points / block, 512 threads, 2 blocks/SM.
//  A: warp=4 pts, lane=ch-pair -> fp16 gather + hmax2 -> x (fp32 smem)
//  B: warp=8 j's (FFMA2 pairs), 2 point passes -> h2
//  C: warp=4 ch (FFMA2 pairs), 2 point passes -> out
// ---------------------------------------------------------------------------
__global__ __launch_bounds__(512, 2) void k2(P2 p) {
    extern __shared__ float sm[];
    float* sw   = sm;               // 8704 (mw1^T 64x132, then mw2^T 128x68)
    float* sxs  = sw   + 8704;      // 64*68 = 4352
    float* sh2  = sxs  + 4352;      // 64*132 = 8448
    float* sscM = sh2  + 8448;      // 128
    float* sshM = sscM + 128;       // -> 21760 floats

    const int tid = threadIdx.x;
    const int w = tid >> 5, l = tid & 31;

    // mw1 transposed: sw[i*132 + j] = mw1[j*64+i]
    for (int idx = tid; idx < 8192; idx += 512) {
        int j = idx >> 6, i = idx & 63;
        sw[i*132 + j] = p.mw1[idx];
    }
    if (tid < HID) {
        float sc = p.mg[tid]*rsqrtf(p.mv[tid]+BN_EPS);
        sscM[tid]=sc; sshM[tid]=p.mb[tid]-p.mm[tid]*sc;
    }

    const int p0 = blockIdx.x*64;
    const int b  = p0 >> 14;
    const int n0 = p0 & (NN-1);

    // ---- Phase A: fp16 gather + edge max ----
    {
        const float sc0 = p.agg_g[2*l  ]*rsqrtf(p.agg_v[2*l  ]+BN_EPS);
        const float sc1 = p.agg_g[2*l+1]*rsqrtf(p.agg_v[2*l+1]+BN_EPS);
        const size_t brow = (size_t)b*NN;
#pragma unroll 1
        for (int i = 0; i < 4; i++) {
            const int lp = w*4 + i;
            const int pt = p0 + lp;
            const __half* rowc = g_f12 + (size_t)pt*128;
            __half2 c1h = *(const __half2*)(rowc + 2*l);
            __half2 c2h = *(const __half2*)(rowc + 64 + 2*l);
            int jreg = 0;
            if (l < KK) jreg = p.qidx[(size_t)pt*KK + l];
            __half2 m1 = __float2half2_rn(-65504.f);
            __half2 m2 = m1;
#pragma unroll
            for (int k = 0; k < KK; k++) {
                int j = __shfl_sync(0xffffffffu, jreg, k);
                const __half* rw = g_f12 + (brow + (size_t)j)*128;
                __half2 v1 = *(const __half2*)(rw + 2*l);
                __half2 v2 = *(const __half2*)(rw + 64 + 2*l);
                m1 = __hmax2(m1, v1);
                m2 = __hmax2(m2, v2);
            }
            float2 m1f = __half22float2(m1), m2f = __half22float2(m2);
            float2 c1f = __half22float2(c1h), c2f = __half22float2(c2h);
            float e0 = (m1f.x - c1f.x) + (m2f.x - c2f.x);
            float e1 = (m1f.y - c1f.y) + (m2f.y - c2f.y);
            float2 bs = *(const float2*)(g_base + (size_t)pt*CC + 2*l);
            sxs[lp*68 + 2*l  ] = bs.x + sc0*e0;
            sxs[lp*68 + 2*l+1] = bs.y + sc1*e1;
        }
    }
    __syncthreads();

    // ---- Phase B: h2 = gelu(bnM(mw1 @ x)) ----
    {
        const float4* x4 = (const float4*)sxs;    // pitch 17 float4
        const int jg = w*8;
        u64 acc[8];
#pragma unroll
        for (int q = 0; q < 8; q++) acc[q] = 0ull;
#pragma unroll
        for (int c4 = 0; c4 < 16; c4++) {
            float4 xa = x4[l*17 + c4];
            float4 xb = x4[(32+l)*17 + c4];
            float xav[4], xbv[4];
            xav[0]=xa.x; xav[1]=xa.y; xav[2]=xa.z; xav[3]=xa.w;
            xbv[0]=xb.x; xbv[1]=xb.y; xbv[2]=xb.z; xbv[3]=xb.w;
            u64 xad[4], xbd[4];
#pragma unroll
            for (int t = 0; t < 4; t++) { PACK2(xad[t], xav[t], xav[t]); PACK2(xbd[t], xbv[t], xbv[t]); }
#pragma unroll
            for (int t = 0; t < 4; t++) {
                int i = 4*c4 + t;
                F4 w0; w0.v = *(const float4*)&sw[i*132 + jg];
                F4 w1; w1.v = *(const float4*)&sw[i*132 + jg + 4];
                FFMA2(acc[0], w0.p[0], xad[t], acc[0]);
                FFMA2(acc[1], w0.p[0], xbd[t], acc[1]);
                FFMA2(acc[2], w0.p[1], xad[t], acc[2]);
                FFMA2(acc[3], w0.p[1], xbd[t], acc[3]);
                FFMA2(acc[4], w1.p[0], xad[t], acc[4]);
                FFMA2(acc[5], w1.p[0], xbd[t], acc[5]);
                FFMA2(acc[6], w1.p[1], xad[t], acc[6]);
                FFMA2(acc[7], w1.p[1], xbd[t], acc[7]);
            }
        }
        float h0[8], h1[8];
        UNPK2(h0[0],h0[1],acc[0]); UNPK2(h1[0],h1[1],acc[1]);
        UNPK2(h0[2],h0[3],acc[2]); UNPK2(h1[2],h1[3],acc[3]);
        UNPK2(h0[4],h0[5],acc[4]); UNPK2(h1[4],h1[5],acc[5]);
        UNPK2(h0[6],h0[7],acc[6]); UNPK2(h1[6],h1[7],acc[7]);
#pragma unroll
        for (int q = 0; q < 8; q++) {
            float sc = sscM[jg+q], sh = sshM[jg+q];
            float y0 = h0[q]*sc + sh;
            float y1 = h1[q]*sc + sh;
            h0[q] = y0 * normcdff(y0);
            h1[q] = y1 * normcdff(y1);
        }
        float4* h4 = (float4*)sh2;                // pitch 33 float4
        h4[l*33      + 2*w    ] = make_float4(h0[0],h0[1],h0[2],h0[3]);
        h4[l*33      + 2*w + 1] = make_float4(h0[4],h0[5],h0[6],h0[7]);
        h4[(32+l)*33 + 2*w    ] = make_float4(h1[0],h1[1],h1[2],h1[3]);
        h4[(32+l)*33 + 2*w + 1] = make_float4(h1[4],h1[5],h1[6],h1[7]);
    }
    __syncthreads();

    // mw2 transposed into same buffer: sw[j*68 + c] = mw2[c*128+j]
    for (int idx = tid; idx < 8192; idx += 512) {
        int c = idx >> 7, j = idx & 127;
        sw[j*68 + c] = p.mw2[idx];
    }
    __syncthreads();

    // ---- Phase C: out = x + mw2 @ h2 ----
    {
        const float4* h4 = (const float4*)sh2;
        const int cg = w*4;
        u64 acc[4] = {0ull,0ull,0ull,0ull};
#pragma unroll
        for (int j4 = 0; j4 < 32; j4++) {
            float4 ha = h4[l*33 + j4];
            float4 hb = h4[(32+l)*33 + j4];
            float hav[4], hbv[4];
            hav[0]=ha.x; hav[1]=ha.y; hav[2]=ha.z; hav[3]=ha.w;
            hbv[0]=hb.x; hbv[1]=hb.y; hbv[2]=hb.z; hbv[3]=hb.w;
            u64 had[4], hbd[4];
#pragma unroll
            for (int t = 0; t < 4; t++) { PACK2(had[t], hav[t], hav[t]); PACK2(hbd[t], hbv[t], hbv[t]); }
#pragma unroll
            for (int t = 0; t < 4; t++) {
                int j = 4*j4 + t;
                F4 wv; wv.v = *(const float4*)&sw[j*68 + cg];
                FFMA2(acc[0], wv.p[0], had[t], acc[0]);
                FFMA2(acc[1], wv.p[0], hbd[t], acc[1]);
                FFMA2(acc[2], wv.p[1], had[t], acc[2]);
                FFMA2(acc[3], wv.p[1], hbd[t], acc[3]);
            }
        }
        float o00,o01,o10,o11,o02,o03,o12v,o13;
        UNPK2(o00,o01,acc[0]); UNPK2(o10,o11,acc[1]);
        UNPK2(o02,o03,acc[2]); UNPK2(o12v,o13,acc[3]);
        const size_t obase = (size_t)b*CC*NN;
        float oa0[4] = {o00,o01,o02,o03};
        float oa1[4] = {o10,o11,o12v,o13};
#pragma unroll
        for (int q = 0; q < 4; q++) {
            int ch = cg + q;
            float x0 = sxs[l*68 + ch];
            float x1 = sxs[(32+l)*68 + ch];
            p.out[obase + (size_t)ch*NN + n0 + l     ] = x0 + oa0[q];
            p.out[obase + (size_t)ch*NN + n0 + 32 + l] = x1 + oa1[q];
        }
    }
}

// ---------------------------------------------------------------------------
extern "C" void kernel_launch(void* const* d_in, const int* in_sizes, int n_in,
                              void* d_out, int out_size) {
    const float* f        = (const float*)d_in[0];
    const float* dp       = (const float*)d_in[1];
    const int*   qidx     = (const int*)  d_in[2];
    const float* dirv     = (const float*)d_in[3];
    const float* de_w1    = (const float*)d_in[4];
    const float* de_g1    = (const float*)d_in[5];
    const float* de_b1    = (const float*)d_in[6];
    const float* de_m1    = (const float*)d_in[7];
    const float* de_v1    = (const float*)d_in[8];
    const float* de_w2    = (const float*)d_in[9];
    const float* de_bias2 = (const float*)d_in[10];
    const float* w1       = (const float*)d_in[11];
    const float* b1       = (const float*)d_in[12];
    const float* w2       = (const float*)d_in[13];
    const float* b2       = (const float*)d_in[14];
    const float* w3       = (const float*)d_in[15];
    const float* b3       = (const float*)d_in[16];
    const float* agg_g    = (const float*)d_in[17];
    const float* agg_b    = (const float*)d_in[18];
    const float* agg_m    = (const float*)d_in[19];
    const float* agg_v    = (const float*)d_in[20];
    const float* mw1      = (const float*)d_in[21];
    const float* mg       = (const float*)d_in[22];
    const float* mb       = (const float*)d_in[23];
    const float* mm       = (const float*)d_in[24];
    const float* mv       = (const float*)d_in[25];
    const float* mw2      = (const float*)d_in[26];

    P1 p1;
    p1.f=f; p1.dp=dp; p1.dirv=dirv;
    p1.de_w1=de_w1; p1.de_g1=de_g1; p1.de_b1=de_b1; p1.de_m1=de_m1; p1.de_v1=de_v1;
    p1.de_w2=de_w2; p1.de_bias2=de_bias2;
    p1.w1=w1; p1.b1=b1; p1.w2=w2; p1.b2=b2; p1.w3=w3; p1.b3=b3;
    p1.agg_g=agg_g; p1.agg_b=agg_b; p1.agg_m=agg_m; p1.agg_v=agg_v;

    P2 p2;
    p2.qidx=qidx; p2.agg_g=agg_g; p2.agg_v=agg_v;
    p2.mw1=mw1; p2.mg=mg; p2.mb=mb; p2.mm=mm; p2.mv=mv; p2.mw2=mw2;
    p2.out=(float*)d_out;

    const size_t smem1 = 16832 * sizeof(float);   // 67328 B
    const size_t smem2 = 21760 * sizeof(float);   // 87040 B
    cudaFuncSetAttribute(k1, cudaFuncAttributeMaxDynamicSharedMemorySize, (int)smem1);
    cudaFuncSetAttribute(k2, cudaFuncAttributeMaxDynamicSharedMemorySize, (int)smem2);

    k1<<<NPTS/256, 256, smem1>>>(p1);
    k2<<<NPTS/64, 512, smem2>>>(p2);
}

// round 5
// speedup vs baseline: 1.3449x; 1.1291x over previous
#include <cuda_runtime.h>
#include <cuda_fp16.h>
#include <math.h>

// Problem constants
#define BB   8
#define NN   16384
#define KK   16
#define CC   64
#define MM   32
#define HH   32
#define HID  128
#define NPTS (BB*NN)          // 131072
#define BN_EPS 1e-5f

typedef unsigned long long u64;

// Packed fp32x2 FMA (Blackwell FFMA2) — only reachable via PTX fma.rn.f32x2
#define FFMA2(d,a,b,c) asm("fma.rn.f32x2 %0, %1, %2, %3;" : "=l"(d) : "l"(a), "l"(b), "l"(c))
#define PACK2(d,lo,hi) asm("mov.b64 %0, {%1, %2};" : "=l"(d) : "f"(lo), "f"(hi))
#define UNPK2(lo,hi,d) asm("mov.b64 {%0, %1}, %2;" : "=f"(lo), "=f"(hi) : "l"(d))

union F4 { float4 v; u64 p[2]; };

__device__ __forceinline__ float gelu_exact(float y) {
    return 0.5f * y * (1.0f + erff(y * 0.70710678118654752f));
}

// Scratch: interleaved fp16 rows per point: [{f1[2c],f1[2c+1],f2[2c],f2[2c+1]} c=0..31]
// (256B/point). base fp32 point-major.
__device__ __half g_f12[(size_t)NPTS*128];
__device__ float  g_base[(size_t)NPTS*CC];

struct P1 {
    const float *f, *dp, *dirv;
    const float *de_w1, *de_g1, *de_b1, *de_m1, *de_v1, *de_w2, *de_bias2;
    const float *w1, *b1, *w2, *b2, *w3, *b3;
    const float *agg_g, *agg_b, *agg_m, *agg_v;
};

struct P2 {
    const int*   qidx;
    const float *agg_g, *agg_v;
    const float *mw1, *mg, *mb, *mm, *mv, *mw2;
    float* out;
};

// ---------------------------------------------------------------------------
// Kernel 1: thread-per-point.  theta_max -> DE mlp -> f1/f2/f3 (FFMA2),
// writes f1,f2 interleaved fp16 + base fp32.  h staged in smem (regs ~100).
// ---------------------------------------------------------------------------
__global__ __launch_bounds__(256, 2) void k1(P1 p) {
    extern __shared__ float sm[];
    float* swt1  = sm;              // 64*68 = 4352  transposed w1 [i][c]
    float* swt2  = swt1 + 4352;
    float* swt3  = swt2 + 4352;
    float* sdw2t = swt3 + 4352;     // 32*68 = 2176  transposed de_w2 [j][c]
    float* sdw1  = sdw2t + 2176;    // 1024  (H x M row-major)
    float* svv   = sdw1 + 1024;     // 128   (M x float4)
    float* shst  = svv  + 128;      // 256*33 = 8448  per-thread h staging
    float* sb1   = shst + 8448;     // 64
    float* sb2   = sb1  + 64;
    float* sb3   = sb2  + 64;
    float* sbias2= sb3  + 64;
    float* ssc1  = sbias2 + 64;     // 32
    float* ssh1  = ssc1 + 32;
    float* sscA  = ssh1 + 32;       // 64
    float* sshA  = sscA + 64;       // -> 25280 floats total (101120 B)

    const int tid = threadIdx.x;
    for (int idx = tid; idx < 4096; idx += 256) {
        int c = idx >> 6, i = idx & 63;
        swt1[i*68+c] = p.w1[idx];
        swt2[i*68+c] = p.w2[idx];
        swt3[i*68+c] = p.w3[idx];
    }
    for (int idx = tid; idx < 2048; idx += 256) {   // de_w2 is [c][j], 64x32
        int c = idx >> 5, j = idx & 31;
        sdw2t[j*68+c] = p.de_w2[idx];
    }
    for (int i = tid; i < 1024; i += 256) sdw1[i] = p.de_w1[i];
    if (tid < 64) {
        sb1[tid]=p.b1[tid]; sb2[tid]=p.b2[tid]; sb3[tid]=p.b3[tid];
        sbias2[tid]=p.de_bias2[tid];
        float sc = p.agg_g[tid]*rsqrtf(p.agg_v[tid]+BN_EPS);
        sscA[tid]=sc; sshA[tid]=p.agg_b[tid]-p.agg_m[tid]*sc;
    }
    if (tid < 32) {
        float v0=p.dirv[tid*3+0], v1=p.dirv[tid*3+1], v2=p.dirv[tid*3+2];
        float inv = rsqrtf(fmaxf(v0*v0+v1*v1+v2*v2, 1e-24f));
        svv[tid*4+0]=v0*inv; svv[tid*4+1]=v1*inv; svv[tid*4+2]=v2*inv; svv[tid*4+3]=0.f;
        float sc = p.de_g1[tid]*rsqrtf(p.de_v1[tid]+BN_EPS);
        ssc1[tid]=sc; ssh1[tid]=p.de_b1[tid]-p.de_m1[tid]*sc;
    }
    __syncthreads();

    const int pt = blockIdx.x*256 + tid;
    const int b  = pt >> 14;
    const int n  = pt & (NN-1);

    // ---- load + normalize dp (16 neighbors x 3 dims) ----
    float xn0[KK], xn1[KK], xn2[KK];
    const float4* dp4 = (const float4*)(p.dp + (size_t)b*3*NN*KK + (size_t)n*KK);
#pragma unroll
    for (int k4 = 0; k4 < 4; k4++) {
        float4 A = dp4[k4];
        float4 Bv= dp4[(NN*KK/4) + k4];
        float4 Cv= dp4[(2*NN*KK/4) + k4];
        float ax[4]={A.x,A.y,A.z,A.w}, bx[4]={Bv.x,Bv.y,Bv.z,Bv.w}, cx[4]={Cv.x,Cv.y,Cv.z,Cv.w};
#pragma unroll
        for (int kk = 0; kk < 4; kk++) {
            float x0=ax[kk], x1=bx[kk], x2=cx[kk];
            float inv = rsqrtf(fmaxf(x0*x0+x1*x1+x2*x2, 1e-24f));
            xn0[4*k4+kk]=x0*inv; xn1[4*k4+kk]=x1*inv; xn2[4*k4+kk]=x2*inv;
        }
    }

    // ---- theta_max (m outer, one float4 broadcast per m) ----
    float tm[MM];
    const float4* sv4 = (const float4*)svv;
#pragma unroll
    for (int m = 0; m < MM; m++) {
        float4 v = sv4[m];
        float acc = -INFINITY;
#pragma unroll
        for (int k = 0; k < KK; k++)
            acc = fmaxf(acc, v.x*xn0[k] + v.y*xn1[k] + v.z*xn2[k]);
        tm[m] = acc;
    }

    // ---- h = gelu(bn1(de_w1 @ tm)) -> smem staging (frees regs) ----
    {
        const float4* sdw1_4 = (const float4*)sdw1;
        float* myh = shst + tid*33;
#pragma unroll
        for (int j = 0; j < HH; j++) {
            float acc = 0.f;
#pragma unroll
            for (int m4 = 0; m4 < 8; m4++) {
                float4 w = sdw1_4[j*8 + m4];
                acc += w.x*tm[4*m4] + w.y*tm[4*m4+1] + w.z*tm[4*m4+2] + w.w*tm[4*m4+3];
            }
            float y = acc*ssc1[j] + ssh1[j];
            myh[j] = gelu_exact(y);
        }
    }

    // ---- f row into registers (coalesced: stride NN across lanes) ----
    float fv[CC];
    const float* fb = p.f + (size_t)b*CC*NN + n;
#pragma unroll
    for (int i = 0; i < CC; i++) fv[i] = fb[(size_t)i*NN];

    __half* o12 = g_f12 + (size_t)pt*128;
    float*  ob  = g_base + (size_t)pt*CC;
    const float* myh = shst + tid*33;

#pragma unroll 1
    for (int c0 = 0; c0 < CC; c0 += 4) {
        u64 a1p0,a1p1,a2p0,a2p1,a3p0,a3p1,app0,app1;
        PACK2(a1p0, sb1[c0], sb1[c0+1]);    PACK2(a1p1, sb1[c0+2], sb1[c0+3]);
        PACK2(a2p0, sb2[c0], sb2[c0+1]);    PACK2(a2p1, sb2[c0+2], sb2[c0+3]);
        PACK2(a3p0, sb3[c0], sb3[c0+1]);    PACK2(a3p1, sb3[c0+2], sb3[c0+3]);
        PACK2(app0, sbias2[c0], sbias2[c0+1]); PACK2(app1, sbias2[c0+2], sbias2[c0+3]);
#pragma unroll
        for (int i = 0; i < CC; i++) {
            u64 xd; PACK2(xd, fv[i], fv[i]);
            F4 wa; wa.v = *(const float4*)&swt1[i*68 + c0];
            FFMA2(a1p0, wa.p[0], xd, a1p0);
            FFMA2(a1p1, wa.p[1], xd, a1p1);
            F4 wb; wb.v = *(const float4*)&swt2[i*68 + c0];
            FFMA2(a2p0, wb.p[0], xd, a2p0);
            FFMA2(a2p1, wb.p[1], xd, a2p1);
            F4 wc; wc.v = *(const float4*)&swt3[i*68 + c0];
            FFMA2(a3p0, wc.p[0], xd, a3p0);
            FFMA2(a3p1, wc.p[1], xd, a3p1);
        }
#pragma unroll
        for (int j = 0; j < HH; j++) {
            float hj = myh[j];
            u64 hd; PACK2(hd, hj, hj);
            F4 wp; wp.v = *(const float4*)&sdw2t[j*68 + c0];
            FFMA2(app0, wp.p[0], hd, app0);
            FFMA2(app1, wp.p[1], hd, app1);
        }
        float f1a,f1b,f1c,f1d, f2a,f2b,f2c,f2d, f3a,f3b,f3c,f3d, pa,pb,pc,pd;
        UNPK2(f1a,f1b,a1p0); UNPK2(f1c,f1d,a1p1);
        UNPK2(f2a,f2b,a2p0); UNPK2(f2c,f2d,a2p1);
        UNPK2(f3a,f3b,a3p0); UNPK2(f3c,f3d,a3p1);
        UNPK2(pa,pb,app0);   UNPK2(pc,pd,app1);

        // interleaved fp16 write: [2*c0 .. ] = {f1 pair, f2 pair} per channel-pair
        {
            __half2 t1 = __floats2half2_rn(f1a,f1b);
            __half2 t2 = __floats2half2_rn(f2a,f2b);
            uint2 pk; pk.x = *(unsigned*)&t1; pk.y = *(unsigned*)&t2;
            *(uint2*)(o12 + 2*c0) = pk;
            __half2 t3 = __floats2half2_rn(f1c,f1d);
            __half2 t4 = __floats2half2_rn(f2c,f2d);
            uint2 pk2; pk2.x = *(unsigned*)&t3; pk2.y = *(unsigned*)&t4;
            *(uint2*)(o12 + 2*c0 + 4) = pk2;
        }

        // base: reload f from global (L1 hit, coalesced) — avoids dynamic reg index
        float fo0 = fb[(size_t)(c0  )*NN];
        float fo1 = fb[(size_t)(c0+1)*NN];
        float fo2 = fb[(size_t)(c0+2)*NN];
        float fo3 = fb[(size_t)(c0+3)*NN];
        float b0 = fo0 + pa + sscA[c0  ]*(f2a+f3a) + sshA[c0  ];
        float b1v= fo1 + pb + sscA[c0+1]*(f2b+f3b) + sshA[c0+1];
        float b2v= fo2 + pc + sscA[c0+2]*(f2c+f3c) + sshA[c0+2];
        float b3v= fo3 + pd + sscA[c0+3]*(f2d+f3d) + sshA[c0+3];
        *(float4*)(ob + c0) = make_float4(b0,b1v,b2v,b3v);
    }
}

// ---------------------------------------------------------------------------
// Kernel 2: 64 points / block, 512 threads, 2 blocks/SM.
//  A: warp=4 pts, lane=ch-pair -> one LDG.64/neighbor (interleaved fp16) + hmax2
//  B: warp=8 j's (FFMA2 pairs), 2 point passes -> h2
//  C: warp=4 ch (FFMA2 pairs), 2 point passes -> out
// ---------------------------------------------------------------------------
__global__ __launch_bounds__(512, 2) void k2(P2 p) {
    extern __shared__ float sm[];
    float* sw   = sm;               // 8704 (mw1^T 64x132, then mw2^T 128x68)
    float* sxs  = sw   + 8704;      // 64*68 = 4352
    float* sh2  = sxs  + 4352;      // 64*132 = 8448
    float* sscM = sh2  + 8448;      // 128
    float* sshM = sscM + 128;       // -> 21760 floats

    const int tid = threadIdx.x;
    const int w = tid >> 5, l = tid & 31;

    // mw1 transposed: sw[i*132 + j] = mw1[j*64+i]
    for (int idx = tid; idx < 8192; idx += 512) {
        int j = idx >> 6, i = idx & 63;
        sw[i*132 + j] = p.mw1[idx];
    }
    if (tid < HID) {
        float sc = p.mg[tid]*rsqrtf(p.mv[tid]+BN_EPS);
        sscM[tid]=sc; sshM[tid]=p.mb[tid]-p.mm[tid]*sc;
    }

    const int p0 = blockIdx.x*64;
    const int b  = p0 >> 14;
    const int n0 = p0 & (NN-1);

    // ---- Phase A: interleaved fp16 gather + edge max ----
    {
        const float sc0 = p.agg_g[2*l  ]*rsqrtf(p.agg_v[2*l  ]+BN_EPS);
        const float sc1 = p.agg_g[2*l+1]*rsqrtf(p.agg_v[2*l+1]+BN_EPS);
        const size_t brow = (size_t)b*NN;
#pragma unroll 1
        for (int i = 0; i < 4; i++) {
            const int lp = w*4 + i;
            const int pt = p0 + lp;
            uint2 cpk = *(const uint2*)(g_f12 + (size_t)pt*128 + 4*l);
            __half2 c1h = *(__half2*)&cpk.x;
            __half2 c2h = *(__half2*)&cpk.y;
            int jreg = 0;
            if (l < KK) jreg = p.qidx[(size_t)pt*KK + l];
            __half2 m1 = __float2half2_rn(-65504.f);
            __half2 m2 = m1;
#pragma unroll
            for (int k = 0; k < KK; k++) {
                int j = __shfl_sync(0xffffffffu, jreg, k);
                uint2 vpk = *(const uint2*)(g_f12 + (brow + (size_t)j)*128 + 4*l);
                m1 = __hmax2(m1, *(__half2*)&vpk.x);
                m2 = __hmax2(m2, *(__half2*)&vpk.y);
            }
            float2 m1f = __half22float2(m1), m2f = __half22float2(m2);
            float2 c1f = __half22float2(c1h), c2f = __half22float2(c2h);
            float e0 = (m1f.x - c1f.x) + (m2f.x - c2f.x);
            float e1 = (m1f.y - c1f.y) + (m2f.y - c2f.y);
            float2 bs = *(const float2*)(g_base + (size_t)pt*CC + 2*l);
            sxs[lp*68 + 2*l  ] = bs.x + sc0*e0;
            sxs[lp*68 + 2*l+1] = bs.y + sc1*e1;
        }
    }
    __syncthreads();

    // ---- Phase B: h2 = gelu(bnM(mw1 @ x)) ----
    {
        const float4* x4 = (const float4*)sxs;    // pitch 17 float4
        const int jg = w*8;
        u64 acc[8];
#pragma unroll
        for (int q = 0; q < 8; q++) acc[q] = 0ull;
#pragma unroll
        for (int c4 = 0; c4 < 16; c4++) {
            float4 xa = x4[l*17 + c4];
            float4 xb = x4[(32+l)*17 + c4];
            float xav[4], xbv[4];
            xav[0]=xa.x; xav[1]=xa.y; xav[2]=xa.z; xav[3]=xa.w;
            xbv[0]=xb.x; xbv[1]=xb.y; xbv[2]=xb.z; xbv[3]=xb.w;
            u64 xad[4], xbd[4];
#pragma unroll
            for (int t = 0; t < 4; t++) { PACK2(xad[t], xav[t], xav[t]); PACK2(xbd[t], xbv[t], xbv[t]); }
#pragma unroll
            for (int t = 0; t < 4; t++) {
                int i = 4*c4 + t;
                F4 w0; w0.v = *(const float4*)&sw[i*132 + jg];
                F4 w1; w1.v = *(const float4*)&sw[i*132 + jg + 4];
                FFMA2(acc[0], w0.p[0], xad[t], acc[0]);
                FFMA2(acc[1], w0.p[0], xbd[t], acc[1]);
                FFMA2(acc[2], w0.p[1], xad[t], acc[2]);
                FFMA2(acc[3], w0.p[1], xbd[t], acc[3]);
                FFMA2(acc[4], w1.p[0], xad[t], acc[4]);
                FFMA2(acc[5], w1.p[0], xbd[t], acc[5]);
                FFMA2(acc[6], w1.p[1], xad[t], acc[6]);
                FFMA2(acc[7], w1.p[1], xbd[t], acc[7]);
            }
        }
        float h0[8], h1[8];
        UNPK2(h0[0],h0[1],acc[0]); UNPK2(h1[0],h1[1],acc[1]);
        UNPK2(h0[2],h0[3],acc[2]); UNPK2(h1[2],h1[3],acc[3]);
        UNPK2(h0[4],h0[5],acc[4]); UNPK2(h1[4],h1[5],acc[5]);
        UNPK2(h0[6],h0[7],acc[6]); UNPK2(h1[6],h1[7],acc[7]);
#pragma unroll
        for (int q = 0; q < 8; q++) {
            float sc = sscM[jg+q], sh = sshM[jg+q];
            h0[q] = gelu_exact(h0[q]*sc + sh);
            h1[q] = gelu_exact(h1[q]*sc + sh);
        }
        float4* h4 = (float4*)sh2;                // pitch 33 float4
        h4[l*33      + 2*w    ] = make_float4(h0[0],h0[1],h0[2],h0[3]);
        h4[l*33      + 2*w + 1] = make_float4(h0[4],h0[5],h0[6],h0[7]);
        h4[(32+l)*33 + 2*w    ] = make_float4(h1[0],h1[1],h1[2],h1[3]);
        h4[(32+l)*33 + 2*w + 1] = make_float4(h1[4],h1[5],h1[6],h1[7]);
    }
    __syncthreads();

    // mw2 transposed into same buffer: sw[j*68 + c] = mw2[c*128+j]
    for (int idx = tid; idx < 8192; idx += 512) {
        int c = idx >> 7, j = idx & 127;
        sw[j*68 + c] = p.mw2[idx];
    }
    __syncthreads();

    // ---- Phase C: out = x + mw2 @ h2 ----
    {
        const float4* h4 = (const float4*)sh2;
        const int cg = w*4;
        u64 acc[4] = {0ull,0ull,0ull,0ull};
#pragma unroll
        for (int j4 = 0; j4 < 32; j4++) {
            float4 ha = h4[l*33 + j4];
            float4 hb = h4[(32+l)*33 + j4];
            float hav[4], hbv[4];
            hav[0]=ha.x; hav[1]=ha.y; hav[2]=ha.z; hav[3]=ha.w;
            hbv[0]=hb.x; hbv[1]=hb.y; hbv[2]=hb.z; hbv[3]=hb.w;
            u64 had[4], hbd[4];
#pragma unroll
            for (int t = 0; t < 4; t++) { PACK2(had[t], hav[t], hav[t]); PACK2(hbd[t], hbv[t], hbv[t]); }
#pragma unroll
            for (int t = 0; t < 4; t++) {
                int j = 4*j4 + t;
                F4 wv; wv.v = *(const float4*)&sw[j*68 + cg];
                FFMA2(acc[0], wv.p[0], had[t], acc[0]);
                FFMA2(acc[1], wv.p[0], hbd[t], acc[1]);
                FFMA2(acc[2], wv.p[1], had[t], acc[2]);
                FFMA2(acc[3], wv.p[1], hbd[t], acc[3]);
            }
        }
        float o00,o01,o10,o11,o02,o03,o12v,o13;
        UNPK2(o00,o01,acc[0]); UNPK2(o10,o11,acc[1]);
        UNPK2(o02,o03,acc[2]); UNPK2(o12v,o13,acc[3]);
        const size_t obase = (size_t)b*CC*NN;
        float oa0[4] = {o00,o01,o02,o03};
        float oa1[4] = {o10,o11,o12v,o13};
#pragma unroll
        for (int q = 0; q < 4; q++) {
            int ch = cg + q;
            float x0 = sxs[l*68 + ch];
            float x1 = sxs[(32+l)*68 + ch];
            p.out[obase + (size_t)ch*NN + n0 + l     ] = x0 + oa0[q];
            p.out[obase + (size_t)ch*NN + n0 + 32 + l] = x1 + oa1[q];
        }
    }
}

// ---------------------------------------------------------------------------
extern "C" void kernel_launch(void* const* d_in, const int* in_sizes, int n_in,
                              void* d_out, int out_size) {
    const float* f        = (const float*)d_in[0];
    const float* dp       = (const float*)d_in[1];
    const int*   qidx     = (const int*)  d_in[2];
    const float* dirv     = (const float*)d_in[3];
    const float* de_w1    = (const float*)d_in[4];
    const float* de_g1    = (const float*)d_in[5];
    const float* de_b1    = (const float*)d_in[6];
    const float* de_m1    = (const float*)d_in[7];
    const float* de_v1    = (const float*)d_in[8];
    const float* de_w2    = (const float*)d_in[9];
    const float* de_bias2 = (const float*)d_in[10];
    const float* w1       = (const float*)d_in[11];
    const float* b1       = (const float*)d_in[12];
    const float* w2       = (const float*)d_in[13];
    const float* b2       = (const float*)d_in[14];
    const float* w3       = (const float*)d_in[15];
    const float* b3       = (const float*)d_in[16];
    const float* agg_g    = (const float*)d_in[17];
    const float* agg_b    = (const float*)d_in[18];
    const float* agg_m    = (const float*)d_in[19];
    const float* agg_v    = (const float*)d_in[20];
    const float* mw1      = (const float*)d_in[21];
    const float* mg       = (const float*)d_in[22];
    const float* mb       = (const float*)d_in[23];
    const float* mm       = (const float*)d_in[24];
    const float* mv       = (const float*)d_in[25];
    const float* mw2      = (const float*)d_in[26];

    P1 p1;
    p1.f=f; p1.dp=dp; p1.dirv=dirv;
    p1.de_w1=de_w1; p1.de_g1=de_g1; p1.de_b1=de_b1; p1.de_m1=de_m1; p1.de_v1=de_v1;
    p1.de_w2=de_w2; p1.de_bias2=de_bias2;
    p1.w1=w1; p1.b1=b1; p1.w2=w2; p1.b2=b2; p1.w3=w3; p1.b3=b3;
    p1.agg_g=agg_g; p1.agg_b=agg_b; p1.agg_m=agg_m; p1.agg_v=agg_v;

    P2 p2;
    p2.qidx=qidx; p2.agg_g=agg_g; p2.agg_v=agg_v;
    p2.mw1=mw1; p2.mg=mg; p2.mb=mb; p2.mm=mm; p2.mv=mv; p2.mw2=mw2;
    p2.out=(float*)d_out;

    const size_t smem1 = 25280 * sizeof(float);   // 101120 B
    const size_t smem2 = 21760 * sizeof(float);   // 87040 B
    cudaFuncSetAttribute(k1, cudaFuncAttributeMaxDynamicSharedMemorySize, (int)smem1);
    cudaFuncSetAttribute(k2, cudaFuncAttributeMaxDynamicSharedMemorySize, (int)smem2);

    k1<<<NPTS/256, 256, smem1>>>(p1);
    k2<<<NPTS/64, 512, smem2>>>(p2);
}

// round 6
// speedup vs baseline: 1.8369x; 1.3658x over previous
#include <cuda_runtime.h>
#include <cuda_fp16.h>
#include <math.h>

// Problem constants
#define BB   8
#define NN   16384
#define KK   16
#define CC   64
#define MM   32
#define HH   32
#define HID  128
#define NPTS (BB*NN)          // 131072
#define BN_EPS 1e-5f

typedef unsigned long long u64;

// Packed fp32x2 FMA (k2 only)
#define FFMA2(d,a,b,c) asm("fma.rn.f32x2 %0, %1, %2, %3;" : "=l"(d) : "l"(a), "l"(b), "l"(c))
#define PACK2(d,lo,hi) asm("mov.b64 %0, {%1, %2};" : "=l"(d) : "f"(lo), "f"(hi))
#define UNPK2(lo,hi,d) asm("mov.b64 {%0, %1}, %2;" : "=f"(lo), "=f"(hi) : "l"(d))

union F4 { float4 v; u64 p[2]; };

__device__ __forceinline__ float gelu_exact(float y) {
    return 0.5f * y * (1.0f + erff(y * 0.70710678118654752f));
}

__device__ __forceinline__ unsigned h2u(__half2 h) { return *(unsigned*)&h; }

// m16n8k16 fp16 MMA, fp32 accumulate (legacy HMMA path on sm_103a)
__device__ __forceinline__ void mma16816(float d[4], const unsigned a[4],
                                         unsigned b0, unsigned b1) {
    asm volatile("mma.sync.aligned.m16n8k16.row.col.f32.f16.f16.f32 "
        "{%0,%1,%2,%3}, {%4,%5,%6,%7}, {%8,%9}, {%0,%1,%2,%3};"
        : "+f"(d[0]), "+f"(d[1]), "+f"(d[2]), "+f"(d[3])
        : "r"(a[0]), "r"(a[1]), "r"(a[2]), "r"(a[3]), "r"(b0), "r"(b1));
}

// Scratch: interleaved fp16 rows per point: [{f1[2c],f1[2c+1],f2[2c],f2[2c+1]} c=0..31]
// (256B/point). base fp32 point-major.
__device__ __half g_f12[(size_t)NPTS*128];
__device__ float  g_base[(size_t)NPTS*CC];

struct P1 {
    const float *f, *dp, *dirv;
    const float *de_w1, *de_g1, *de_b1, *de_m1, *de_v1, *de_w2, *de_bias2;
    const float *w1, *b1, *w2, *b2, *w3, *b3;
    const float *agg_g, *agg_b, *agg_m, *agg_v;
};

struct P2 {
    const int*   qidx;
    const float *agg_g, *agg_v;
    const float *mw1, *mg, *mb, *mm, *mv, *mw2;
    float* out;
};

// ---------------------------------------------------------------------------
// Kernel 1 (tensor-core): 256 threads, 256 points / block.
//  stage 1 (thread=point): theta_max -> h (fp32) -> hA fp16 smem; f -> xA fp16 smem
//  stage 2 (warp-MMA): f1/f2/f3 = W{1,2,3}@f, pe = de_w2@h, via m16n8k16 HMMA,
//    fp32 accumulators initialized with biases. Epilogue writes g_f12 (fp16
//    interleaved) + g_base (fp32, base = f + pe + scA*(f2+f3) + shA).
// smem fragment pitches chosen conflict-free: x/W rows 72 halves, h/dw 40 halves.
// ---------------------------------------------------------------------------
__global__ __launch_bounds__(256) void k1(P1 p) {
    extern __shared__ char smbase[];
    float* sdw1   = (float*)smbase;            // 1024  de_w1 [32j][32m]
    float* svv    = sdw1 + 1024;               // 128   dir vecs (float4/m)
    float* sb1    = svv  + 128;                // 64
    float* sb2    = sb1  + 64;
    float* sb3    = sb2  + 64;
    float* sbias2 = sb3  + 64;                 // 64
    float* ssc1   = sbias2 + 64;               // 32
    float* ssh1   = ssc1 + 32;                 // 32
    float* sscA   = ssh1 + 32;                 // 64
    float* sshA   = sscA + 64;                 // 64 -> 1600 floats (6400 B)
    __half* xA  = (__half*)(smbase + 6400);    // 256*72 = 18432 h
    __half* hA  = xA  + 18432;                 // 256*40 = 10240 h
    __half* ws1 = hA  + 10240;                 // 64*72 = 4608 h
    __half* ws2 = ws1 + 4608;
    __half* ws3 = ws2 + 4608;
    __half* dws = ws3 + 4608;                  // 64*40 = 2560 h  -> total 96512 B

    const int tid = threadIdx.x;

    // ---- stage weights (fp32 -> fp16) ----
    for (int idx = tid; idx < 4096; idx += 256) {
        int c = idx >> 6, i = idx & 63;
        ws1[c*72+i] = __float2half(p.w1[idx]);
        ws2[c*72+i] = __float2half(p.w2[idx]);
        ws3[c*72+i] = __float2half(p.w3[idx]);
    }
    for (int idx = tid; idx < 2048; idx += 256) {  // de_w2 [64c][32h]
        int c = idx >> 5, h = idx & 31;
        dws[c*40+h] = __float2half(p.de_w2[idx]);
    }
    for (int i = tid; i < 1024; i += 256) sdw1[i] = p.de_w1[i];
    if (tid < 64) {
        sb1[tid]=p.b1[tid]; sb2[tid]=p.b2[tid]; sb3[tid]=p.b3[tid];
        sbias2[tid]=p.de_bias2[tid];
        float sc = p.agg_g[tid]*rsqrtf(p.agg_v[tid]+BN_EPS);
        sscA[tid]=sc; sshA[tid]=p.agg_b[tid]-p.agg_m[tid]*sc;
    }
    if (tid < 32) {
        float v0=p.dirv[tid*3+0], v1=p.dirv[tid*3+1], v2=p.dirv[tid*3+2];
        float inv = rsqrtf(fmaxf(v0*v0+v1*v1+v2*v2, 1e-24f));
        svv[tid*4+0]=v0*inv; svv[tid*4+1]=v1*inv; svv[tid*4+2]=v2*inv; svv[tid*4+3]=0.f;
        float sc = p.de_g1[tid]*rsqrtf(p.de_v1[tid]+BN_EPS);
        ssc1[tid]=sc; ssh1[tid]=p.de_b1[tid]-p.de_m1[tid]*sc;
    }
    __syncthreads();

    const int p0 = blockIdx.x*256;
    const int b  = p0 >> 14;
    const int n0 = p0 & (NN-1);
    const int pt = p0 + tid;
    const int n  = n0 + tid;

    // ---- theta_max (thread = point) ----
    {
        float xn0[KK], xn1[KK], xn2[KK];
        const float4* dp4 = (const float4*)(p.dp + (size_t)b*3*NN*KK + (size_t)n*KK);
#pragma unroll
        for (int k4 = 0; k4 < 4; k4++) {
            float4 A = dp4[k4];
            float4 Bv= dp4[(NN*KK/4) + k4];
            float4 Cv= dp4[(2*NN*KK/4) + k4];
            float ax[4]={A.x,A.y,A.z,A.w}, bx[4]={Bv.x,Bv.y,Bv.z,Bv.w}, cx[4]={Cv.x,Cv.y,Cv.z,Cv.w};
#pragma unroll
            for (int kk = 0; kk < 4; kk++) {
                float x0=ax[kk], x1=bx[kk], x2=cx[kk];
                float inv = rsqrtf(fmaxf(x0*x0+x1*x1+x2*x2, 1e-24f));
                xn0[4*k4+kk]=x0*inv; xn1[4*k4+kk]=x1*inv; xn2[4*k4+kk]=x2*inv;
            }
        }
        float tm[MM];
        const float4* sv4 = (const float4*)svv;
#pragma unroll
        for (int m = 0; m < MM; m++) {
            float4 v = sv4[m];
            float acc = -INFINITY;
#pragma unroll
            for (int k = 0; k < KK; k++)
                acc = fmaxf(acc, v.x*xn0[k] + v.y*xn1[k] + v.z*xn2[k]);
            tm[m] = acc;
        }
        // h = gelu(bn1(de_w1 @ tm)) -> hA fp16 [pt][40]
        const float4* sdw1_4 = (const float4*)sdw1;
#pragma unroll
        for (int j2 = 0; j2 < HH/2; j2++) {
            float hv[2];
#pragma unroll
            for (int q = 0; q < 2; q++) {
                int j = 2*j2 + q;
                float acc = 0.f;
#pragma unroll
                for (int m4 = 0; m4 < 8; m4++) {
                    float4 w = sdw1_4[j*8 + m4];
                    acc += w.x*tm[4*m4] + w.y*tm[4*m4+1] + w.z*tm[4*m4+2] + w.w*tm[4*m4+3];
                }
                hv[q] = gelu_exact(acc*ssc1[j] + ssh1[j]);
            }
            *(unsigned*)&hA[tid*40 + 2*j2] = h2u(__floats2half2_rn(hv[0], hv[1]));
        }
    }

    // ---- stage x tile: f[64ch][pt] -> xA[pt][72] fp16 ----
    {
        const float* fb = p.f + (size_t)b*CC*NN + n;
#pragma unroll
        for (int c2 = 0; c2 < 32; c2++) {
            float v0 = fb[(size_t)(2*c2  )*NN];
            float v1 = fb[(size_t)(2*c2+1)*NN];
            *(unsigned*)&xA[tid*72 + 2*c2] = h2u(__floats2half2_rn(v0, v1));
        }
    }
    __syncthreads();

    // ---- MMA stage: 8 warps, each 2 point-tiles of 16 ----
    const int w  = tid >> 5;
    const int lt = tid & 31;
    const int tq = lt >> 2;       // 0..7
    const int tr = lt & 3;        // 0..3
    const float* fg = p.f + (size_t)b*CC*NN;

#pragma unroll 1
    for (int pti = 0; pti < 2; pti++) {
        const int ptb = (w*2 + pti) * 16;
        // A fragments: x (4 k-steps) and h (2 k-steps)
        unsigned ax[4][4], ah[2][4];
#pragma unroll
        for (int ks = 0; ks < 4; ks++) {
            int r0 = (ptb + tq)*72, r1 = r0 + 8*72;
            int k0 = 16*ks + 2*tr;
            ax[ks][0] = *(const unsigned*)&xA[r0 + k0];
            ax[ks][1] = *(const unsigned*)&xA[r1 + k0];
            ax[ks][2] = *(const unsigned*)&xA[r0 + k0 + 8];
            ax[ks][3] = *(const unsigned*)&xA[r1 + k0 + 8];
        }
#pragma unroll
        for (int ks = 0; ks < 2; ks++) {
            int r0 = (ptb + tq)*40, r1 = r0 + 8*40;
            int k0 = 16*ks + 2*tr;
            ah[ks][0] = *(const unsigned*)&hA[r0 + k0];
            ah[ks][1] = *(const unsigned*)&hA[r1 + k0];
            ah[ks][2] = *(const unsigned*)&hA[r0 + k0 + 8];
            ah[ks][3] = *(const unsigned*)&hA[r1 + k0 + 8];
        }

#pragma unroll 1
        for (int nt = 0; nt < 8; nt++) {
            const int ch0 = nt*8 + tr*2;
            float d1[4], d2[4], d3[4], dpe[4];
            d1[0]=sb1[ch0];   d1[1]=sb1[ch0+1];   d1[2]=d1[0];  d1[3]=d1[1];
            d2[0]=sb2[ch0];   d2[1]=sb2[ch0+1];   d2[2]=d2[0];  d2[3]=d2[1];
            d3[0]=sb3[ch0];   d3[1]=sb3[ch0+1];   d3[2]=d3[0];  d3[3]=d3[1];
            dpe[0]=sbias2[ch0]; dpe[1]=sbias2[ch0+1]; dpe[2]=dpe[0]; dpe[3]=dpe[1];

            const int nrow = (nt*8 + tq)*72;
#pragma unroll
            for (int ks = 0; ks < 4; ks++) {
                const int kb = 16*ks + 2*tr;
                unsigned b0, b1;
                b0 = *(const unsigned*)&ws1[nrow + kb];
                b1 = *(const unsigned*)&ws1[nrow + kb + 8];
                mma16816(d1, ax[ks], b0, b1);
                b0 = *(const unsigned*)&ws2[nrow + kb];
                b1 = *(const unsigned*)&ws2[nrow + kb + 8];
                mma16816(d2, ax[ks], b0, b1);
                b0 = *(const unsigned*)&ws3[nrow + kb];
                b1 = *(const unsigned*)&ws3[nrow + kb + 8];
                mma16816(d3, ax[ks], b0, b1);
            }
            const int drow = (nt*8 + tq)*40;
#pragma unroll
            for (int ks = 0; ks < 2; ks++) {
                const int kb = 16*ks + 2*tr;
                unsigned b0 = *(const unsigned*)&dws[drow + kb];
                unsigned b1 = *(const unsigned*)&dws[drow + kb + 8];
                mma16816(dpe, ah[ks], b0, b1);
            }

            // epilogue: 2 point-rows per thread
#pragma unroll
            for (int r = 0; r < 2; r++) {
                const int lpt = ptb + tq + 8*r;     // block-local point
                const int gpt = p0 + lpt;
                float f1a=d1[2*r], f1b=d1[2*r+1];
                float f2a=d2[2*r], f2b=d2[2*r+1];
                float f3a=d3[2*r], f3b=d3[2*r+1];
                float pea=dpe[2*r], peb=dpe[2*r+1];

                uint2 pk;
                pk.x = h2u(__floats2half2_rn(f1a, f1b));
                pk.y = h2u(__floats2half2_rn(f2a, f2b));
                *(uint2*)(g_f12 + (size_t)gpt*128 + 2*ch0) = pk;

                float fo0 = fg[(size_t)(ch0  )*NN + (n0 + lpt)];
                float fo1 = fg[(size_t)(ch0+1)*NN + (n0 + lpt)];
                float bx = fo0 + pea + sscA[ch0  ]*(f2a+f3a) + sshA[ch0  ];
                float by = fo1 + peb + sscA[ch0+1]*(f2b+f3b) + sshA[ch0+1];
                *(float2*)(g_base + (size_t)gpt*CC + ch0) = make_float2(bx, by);
            }
        }
    }
}

// ---------------------------------------------------------------------------
// Kernel 2 (unchanged from R5): 64 points / block, 512 threads, 2 blocks/SM.
// ---------------------------------------------------------------------------
__global__ __launch_bounds__(512, 2) void k2(P2 p) {
    extern __shared__ float sm[];
    float* sw   = sm;               // 8704 (mw1^T 64x132, then mw2^T 128x68)
    float* sxs  = sw   + 8704;      // 64*68 = 4352
    float* sh2  = sxs  + 4352;      // 64*132 = 8448
    float* sscM = sh2  + 8448;      // 128
    float* sshM = sscM + 128;       // -> 21760 floats

    const int tid = threadIdx.x;
    const int w = tid >> 5, l = tid & 31;

    for (int idx = tid; idx < 8192; idx += 512) {
        int j = idx >> 6, i = idx & 63;
        sw[i*132 + j] = p.mw1[idx];
    }
    if (tid < HID) {
        float sc = p.mg[tid]*rsqrtf(p.mv[tid]+BN_EPS);
        sscM[tid]=sc; sshM[tid]=p.mb[tid]-p.mm[tid]*sc;
    }

    const int p0 = blockIdx.x*64;
    const int b  = p0 >> 14;
    const int n0 = p0 & (NN-1);

    // ---- Phase A: interleaved fp16 gather + edge max ----
    {
        const float sc0 = p.agg_g[2*l  ]*rsqrtf(p.agg_v[2*l  ]+BN_EPS);
        const float sc1 = p.agg_g[2*l+1]*rsqrtf(p.agg_v[2*l+1]+BN_EPS);
        const size_t brow = (size_t)b*NN;
#pragma unroll 1
        for (int i = 0; i < 4; i++) {
            const int lp = w*4 + i;
            const int pt = p0 + lp;
            uint2 cpk = *(const uint2*)(g_f12 + (size_t)pt*128 + 4*l);
            __half2 c1h = *(__half2*)&cpk.x;
            __half2 c2h = *(__half2*)&cpk.y;
            int jreg = 0;
            if (l < KK) jreg = p.qidx[(size_t)pt*KK + l];
            __half2 m1 = __float2half2_rn(-65504.f);
            __half2 m2 = m1;
#pragma unroll
            for (int k = 0; k < KK; k++) {
                int j = __shfl_sync(0xffffffffu, jreg, k);
                uint2 vpk = *(const uint2*)(g_f12 + (brow + (size_t)j)*128 + 4*l);
                m1 = __hmax2(m1, *(__half2*)&vpk.x);
                m2 = __hmax2(m2, *(__half2*)&vpk.y);
            }
            float2 m1f = __half22float2(m1), m2f = __half22float2(m2);
            float2 c1f = __half22float2(c1h), c2f = __half22float2(c2h);
            float e0 = (m1f.x - c1f.x) + (m2f.x - c2f.x);
            float e1 = (m1f.y - c1f.y) + (m2f.y - c2f.y);
            float2 bs = *(const float2*)(g_base + (size_t)pt*CC + 2*l);
            sxs[lp*68 + 2*l  ] = bs.x + sc0*e0;
            sxs[lp*68 + 2*l+1] = bs.y + sc1*e1;
        }
    }
    __syncthreads();

    // ---- Phase B: h2 = gelu(bnM(mw1 @ x)) ----
    {
        const float4* x4 = (const float4*)sxs;    // pitch 17 float4
        const int jg = w*8;
        u64 acc[8];
#pragma unroll
        for (int q = 0; q < 8; q++) acc[q] = 0ull;
#pragma unroll
        for (int c4 = 0; c4 < 16; c4++) {
            float4 xa = x4[l*17 + c4];
            float4 xb = x4[(32+l)*17 + c4];
            float xav[4], xbv[4];
            xav[0]=xa.x; xav[1]=xa.y; xav[2]=xa.z; xav[3]=xa.w;
            xbv[0]=xb.x; xbv[1]=xb.y; xbv[2]=xb.z; xbv[3]=xb.w;
            u64 xad[4], xbd[4];
#pragma unroll
            for (int t = 0; t < 4; t++) { PACK2(xad[t], xav[t], xav[t]); PACK2(xbd[t], xbv[t], xbv[t]); }
#pragma unroll
            for (int t = 0; t < 4; t++) {
                int i = 4*c4 + t;
                F4 w0; w0.v = *(const float4*)&sw[i*132 + jg];
                F4 w1; w1.v = *(const float4*)&sw[i*132 + jg + 4];
                FFMA2(acc[0], w0.p[0], xad[t], acc[0]);
                FFMA2(acc[1], w0.p[0], xbd[t], acc[1]);
                FFMA2(acc[2], w0.p[1], xad[t], acc[2]);
                FFMA2(acc[3], w0.p[1], xbd[t], acc[3]);
                FFMA2(acc[4], w1.p[0], xad[t], acc[4]);
                FFMA2(acc[5], w1.p[0], xbd[t], acc[5]);
                FFMA2(acc[6], w1.p[1], xad[t], acc[6]);
                FFMA2(acc[7], w1.p[1], xbd[t], acc[7]);
            }
        }
        float h0[8], h1[8];
        UNPK2(h0[0],h0[1],acc[0]); UNPK2(h1[0],h1[1],acc[1]);
        UNPK2(h0[2],h0[3],acc[2]); UNPK2(h1[2],h1[3],acc[3]);
        UNPK2(h0[4],h0[5],acc[4]); UNPK2(h1[4],h1[5],acc[5]);
        UNPK2(h0[6],h0[7],acc[6]); UNPK2(h1[6],h1[7],acc[7]);
#pragma unroll
        for (int q = 0; q < 8; q++) {
            float sc = sscM[jg+q], sh = sshM[jg+q];
            h0[q] = gelu_exact(h0[q]*sc + sh);
            h1[q] = gelu_exact(h1[q]*sc + sh);
        }
        float4* h4 = (float4*)sh2;                // pitch 33 float4
        h4[l*33      + 2*w    ] = make_float4(h0[0],h0[1],h0[2],h0[3]);
        h4[l*33      + 2*w + 1] = make_float4(h0[4],h0[5],h0[6],h0[7]);
        h4[(32+l)*33 + 2*w    ] = make_float4(h1[0],h1[1],h1[2],h1[3]);
        h4[(32+l)*33 + 2*w + 1] = make_float4(h1[4],h1[5],h1[6],h1[7]);
    }
    __syncthreads();

    // mw2 transposed into same buffer: sw[j*68 + c] = mw2[c*128+j]
    for (int idx = tid; idx < 8192; idx += 512) {
        int c = idx >> 7, j = idx & 127;
        sw[j*68 + c] = p.mw2[idx];
    }
    __syncthreads();

    // ---- Phase C: out = x + mw2 @ h2 ----
    {
        const float4* h4 = (const float4*)sh2;
        const int cg = w*4;
        u64 acc[4] = {0ull,0ull,0ull,0ull};
#pragma unroll
        for (int j4 = 0; j4 < 32; j4++) {
            float4 ha = h4[l*33 + j4];
            float4 hb = h4[(32+l)*33 + j4];
            float hav[4], hbv[4];
            hav[0]=ha.x; hav[1]=ha.y; hav[2]=ha.z; hav[3]=ha.w;
            hbv[0]=hb.x; hbv[1]=hb.y; hbv[2]=hb.z; hbv[3]=hb.w;
            u64 had[4], hbd[4];
#pragma unroll
            for (int t = 0; t < 4; t++) { PACK2(had[t], hav[t], hav[t]); PACK2(hbd[t], hbv[t], hbv[t]); }
#pragma unroll
            for (int t = 0; t < 4; t++) {
                int j = 4*j4 + t;
                F4 wv; wv.v = *(const float4*)&sw[j*68 + cg];
                FFMA2(acc[0], wv.p[0], had[t], acc[0]);
                FFMA2(acc[1], wv.p[0], hbd[t], acc[1]);
                FFMA2(acc[2], wv.p[1], had[t], acc[2]);
                FFMA2(acc[3], wv.p[1], hbd[t], acc[3]);
            }
        }
        float o00,o01,o10,o11,o02,o03,o12v,o13;
        UNPK2(o00,o01,acc[0]); UNPK2(o10,o11,acc[1]);
        UNPK2(o02,o03,acc[2]); UNPK2(o12v,o13,acc[3]);
        const size_t obase = (size_t)b*CC*NN;
        float oa0[4] = {o00,o01,o02,o03};
        float oa1[4] = {o10,o11,o12v,o13};
#pragma unroll
        for (int q = 0; q < 4; q++) {
            int ch = cg + q;
            float x0 = sxs[l*68 + ch];
            float x1 = sxs[(32+l)*68 + ch];
            p.out[obase + (size_t)ch*NN + n0 + l     ] = x0 + oa0[q];
            p.out[obase + (size_t)ch*NN + n0 + 32 + l] = x1 + oa1[q];
        }
    }
}

// ---------------------------------------------------------------------------
extern "C" void kernel_launch(void* const* d_in, const int* in_sizes, int n_in,
                              void* d_out, int out_size) {
    const float* f        = (const float*)d_in[0];
    const float* dp       = (const float*)d_in[1];
    const int*   qidx     = (const int*)  d_in[2];
    const float* dirv     = (const float*)d_in[3];
    const float* de_w1    = (const float*)d_in[4];
    const float* de_g1    = (const float*)d_in[5];
    const float* de_b1    = (const float*)d_in[6];
    const float* de_m1    = (const float*)d_in[7];
    const float* de_v1    = (const float*)d_in[8];
    const float* de_w2    = (const float*)d_in[9];
    const float* de_bias2 = (const float*)d_in[10];
    const float* w1       = (const float*)d_in[11];
    const float* b1       = (const float*)d_in[12];
    const float* w2       = (const float*)d_in[13];
    const float* b2       = (const float*)d_in[14];
    const float* w3       = (const float*)d_in[15];
    const float* b3       = (const float*)d_in[16];
    const float* agg_g    = (const float*)d_in[17];
    const float* agg_b    = (const float*)d_in[18];
    const float* agg_m    = (const float*)d_in[19];
    const float* agg_v    = (const float*)d_in[20];
    const float* mw1      = (const float*)d_in[21];
    const float* mg       = (const float*)d_in[22];
    const float* mb       = (const float*)d_in[23];
    const float* mm       = (const float*)d_in[24];
    const float* mv       = (const float*)d_in[25];
    const float* mw2      = (const float*)d_in[26];

    P1 p1;
    p1.f=f; p1.dp=dp; p1.dirv=dirv;
    p1.de_w1=de_w1; p1.de_g1=de_g1; p1.de_b1=de_b1; p1.de_m1=de_m1; p1.de_v1=de_v1;
    p1.de_w2=de_w2; p1.de_bias2=de_bias2;
    p1.w1=w1; p1.b1=b1; p1.w2=w2; p1.b2=b2; p1.w3=w3; p1.b3=b3;
    p1.agg_g=agg_g; p1.agg_b=agg_b; p1.agg_m=agg_m; p1.agg_v=agg_v;

    P2 p2;
    p2.qidx=qidx; p2.agg_g=agg_g; p2.agg_v=agg_v;
    p2.mw1=mw1; p2.mg=mg; p2.mb=mb; p2.mm=mm; p2.mv=mv; p2.mw2=mw2;
    p2.out=(float*)d_out;

    const size_t smem1 = 96512;                   // bytes (fp32 + fp16 regions)
    const size_t smem2 = 21760 * sizeof(float);   // 87040 B
    cudaFuncSetAttribute(k1, cudaFuncAttributeMaxDynamicSharedMemorySize, (int)smem1);
    cudaFuncSetAttribute(k2, cudaFuncAttributeMaxDynamicSharedMemorySize, (int)smem2);

    k1<<<NPTS/256, 256, smem1>>>(p1);
    k2<<<NPTS/64, 512, smem2>>>(p2);
}

// round 7
// speedup vs baseline: 2.5134x; 1.3683x over previous
#include <cuda_runtime.h>
#include <cuda_fp16.h>
#include <math.h>

// Problem constants
#define BB   8
#define NN   16384
#define KK   16
#define CC   64
#define MM   32
#define HH   32
#define HID  128
#define NPTS (BB*NN)          // 131072
#define BN_EPS 1e-5f

typedef unsigned long long u64;

__device__ __forceinline__ float gelu_exact(float y) {
    return 0.5f * y * (1.0f + erff(y * 0.70710678118654752f));
}

__device__ __forceinline__ unsigned h2u(__half2 h) { return *(unsigned*)&h; }

// m16n8k16 fp16 MMA, fp32 accumulate
__device__ __forceinline__ void mma16816(float d[4], const unsigned a[4],
                                         unsigned b0, unsigned b1) {
    asm volatile("mma.sync.aligned.m16n8k16.row.col.f32.f16.f16.f32 "
        "{%0,%1,%2,%3}, {%4,%5,%6,%7}, {%8,%9}, {%0,%1,%2,%3};"
        : "+f"(d[0]), "+f"(d[1]), "+f"(d[2]), "+f"(d[3])
        : "r"(a[0]), "r"(a[1]), "r"(a[2]), "r"(a[3]), "r"(b0), "r"(b1));
}

// Scratch: interleaved fp16 rows per point: [{f1[2c],f1[2c+1],f2[2c],f2[2c+1]} c=0..31]
__device__ __half g_f12[(size_t)NPTS*128];
__device__ float  g_base[(size_t)NPTS*CC];

struct P1 {
    const float *f, *dp, *dirv;
    const float *de_w1, *de_g1, *de_b1, *de_m1, *de_v1, *de_w2, *de_bias2;
    const float *w1, *b1, *w2, *b2, *w3, *b3;
    const float *agg_g, *agg_b, *agg_m, *agg_v;
};

struct P2 {
    const int*   qidx;
    const float *agg_g, *agg_v;
    const float *mw1, *mg, *mb, *mm, *mv, *mw2;
    float* out;
};

// ---------------------------------------------------------------------------
// Kernel 1 (tensor-core, unchanged from R6): 256 threads, 256 points / block.
// ---------------------------------------------------------------------------
__global__ __launch_bounds__(256) void k1(P1 p) {
    extern __shared__ char smbase[];
    float* sdw1   = (float*)smbase;            // 1024  de_w1 [32j][32m]
    float* svv    = sdw1 + 1024;               // 128
    float* sb1    = svv  + 128;                // 64
    float* sb2    = sb1  + 64;
    float* sb3    = sb2  + 64;
    float* sbias2 = sb3  + 64;                 // 64
    float* ssc1   = sbias2 + 64;               // 32
    float* ssh1   = ssc1 + 32;                 // 32
    float* sscA   = ssh1 + 32;                 // 64
    float* sshA   = sscA + 64;                 // 64 -> 1600 floats (6400 B)
    __half* xA  = (__half*)(smbase + 6400);    // 256*72
    __half* hA  = xA  + 18432;                 // 256*40
    __half* ws1 = hA  + 10240;                 // 64*72
    __half* ws2 = ws1 + 4608;
    __half* ws3 = ws2 + 4608;
    __half* dws = ws3 + 4608;                  // 64*40 -> total 96512 B

    const int tid = threadIdx.x;

    for (int idx = tid; idx < 4096; idx += 256) {
        int c = idx >> 6, i = idx & 63;
        ws1[c*72+i] = __float2half(p.w1[idx]);
        ws2[c*72+i] = __float2half(p.w2[idx]);
        ws3[c*72+i] = __float2half(p.w3[idx]);
    }
    for (int idx = tid; idx < 2048; idx += 256) {
        int c = idx >> 5, h = idx & 31;
        dws[c*40+h] = __float2half(p.de_w2[idx]);
    }
    for (int i = tid; i < 1024; i += 256) sdw1[i] = p.de_w1[i];
    if (tid < 64) {
        sb1[tid]=p.b1[tid]; sb2[tid]=p.b2[tid]; sb3[tid]=p.b3[tid];
        sbias2[tid]=p.de_bias2[tid];
        float sc = p.agg_g[tid]*rsqrtf(p.agg_v[tid]+BN_EPS);
        sscA[tid]=sc; sshA[tid]=p.agg_b[tid]-p.agg_m[tid]*sc;
    }
    if (tid < 32) {
        float v0=p.dirv[tid*3+0], v1=p.dirv[tid*3+1], v2=p.dirv[tid*3+2];
        float inv = rsqrtf(fmaxf(v0*v0+v1*v1+v2*v2, 1e-24f));
        svv[tid*4+0]=v0*inv; svv[tid*4+1]=v1*inv; svv[tid*4+2]=v2*inv; svv[tid*4+3]=0.f;
        float sc = p.de_g1[tid]*rsqrtf(p.de_v1[tid]+BN_EPS);
        ssc1[tid]=sc; ssh1[tid]=p.de_b1[tid]-p.de_m1[tid]*sc;
    }
    __syncthreads();

    const int p0 = blockIdx.x*256;
    const int b  = p0 >> 14;
    const int n0 = p0 & (NN-1);
    const int n  = n0 + tid;

    // ---- theta_max (thread = point) ----
    {
        float xn0[KK], xn1[KK], xn2[KK];
        const float4* dp4 = (const float4*)(p.dp + (size_t)b*3*NN*KK + (size_t)n*KK);
#pragma unroll
        for (int k4 = 0; k4 < 4; k4++) {
            float4 A = dp4[k4];
            float4 Bv= dp4[(NN*KK/4) + k4];
            float4 Cv= dp4[(2*NN*KK/4) + k4];
            float ax[4]={A.x,A.y,A.z,A.w}, bx[4]={Bv.x,Bv.y,Bv.z,Bv.w}, cx[4]={Cv.x,Cv.y,Cv.z,Cv.w};
#pragma unroll
            for (int kk = 0; kk < 4; kk++) {
                float x0=ax[kk], x1=bx[kk], x2=cx[kk];
                float inv = rsqrtf(fmaxf(x0*x0+x1*x1+x2*x2, 1e-24f));
                xn0[4*k4+kk]=x0*inv; xn1[4*k4+kk]=x1*inv; xn2[4*k4+kk]=x2*inv;
            }
        }
        float tm[MM];
        const float4* sv4 = (const float4*)svv;
#pragma unroll
        for (int m = 0; m < MM; m++) {
            float4 v = sv4[m];
            float acc = -INFINITY;
#pragma unroll
            for (int k = 0; k < KK; k++)
                acc = fmaxf(acc, v.x*xn0[k] + v.y*xn1[k] + v.z*xn2[k]);
            tm[m] = acc;
        }
        const float4* sdw1_4 = (const float4*)sdw1;
#pragma unroll
        for (int j2 = 0; j2 < HH/2; j2++) {
            float hv[2];
#pragma unroll
            for (int q = 0; q < 2; q++) {
                int j = 2*j2 + q;
                float acc = 0.f;
#pragma unroll
                for (int m4 = 0; m4 < 8; m4++) {
                    float4 w = sdw1_4[j*8 + m4];
                    acc += w.x*tm[4*m4] + w.y*tm[4*m4+1] + w.z*tm[4*m4+2] + w.w*tm[4*m4+3];
                }
                hv[q] = gelu_exact(acc*ssc1[j] + ssh1[j]);
            }
            *(unsigned*)&hA[tid*40 + 2*j2] = h2u(__floats2half2_rn(hv[0], hv[1]));
        }
    }

    // ---- stage x tile ----
    {
        const float* fb = p.f + (size_t)b*CC*NN + n;
#pragma unroll
        for (int c2 = 0; c2 < 32; c2++) {
            float v0 = fb[(size_t)(2*c2  )*NN];
            float v1 = fb[(size_t)(2*c2+1)*NN];
            *(unsigned*)&xA[tid*72 + 2*c2] = h2u(__floats2half2_rn(v0, v1));
        }
    }
    __syncthreads();

    const int w  = tid >> 5;
    const int lt = tid & 31;
    const int tq = lt >> 2;
    const int tr = lt & 3;
    const float* fg = p.f + (size_t)b*CC*NN;

#pragma unroll 1
    for (int pti = 0; pti < 2; pti++) {
        const int ptb = (w*2 + pti) * 16;
        unsigned ax[4][4], ah[2][4];
#pragma unroll
        for (int ks = 0; ks < 4; ks++) {
            int r0 = (ptb + tq)*72, r1 = r0 + 8*72;
            int k0 = 16*ks + 2*tr;
            ax[ks][0] = *(const unsigned*)&xA[r0 + k0];
            ax[ks][1] = *(const unsigned*)&xA[r1 + k0];
            ax[ks][2] = *(const unsigned*)&xA[r0 + k0 + 8];
            ax[ks][3] = *(const unsigned*)&xA[r1 + k0 + 8];
        }
#pragma unroll
        for (int ks = 0; ks < 2; ks++) {
            int r0 = (ptb + tq)*40, r1 = r0 + 8*40;
            int k0 = 16*ks + 2*tr;
            ah[ks][0] = *(const unsigned*)&hA[r0 + k0];
            ah[ks][1] = *(const unsigned*)&hA[r1 + k0];
            ah[ks][2] = *(const unsigned*)&hA[r0 + k0 + 8];
            ah[ks][3] = *(const unsigned*)&hA[r1 + k0 + 8];
        }

#pragma unroll 1
        for (int nt = 0; nt < 8; nt++) {
            const int ch0 = nt*8 + tr*2;
            float d1[4], d2[4], d3[4], dpe[4];
            d1[0]=sb1[ch0];   d1[1]=sb1[ch0+1];   d1[2]=d1[0];  d1[3]=d1[1];
            d2[0]=sb2[ch0];   d2[1]=sb2[ch0+1];   d2[2]=d2[0];  d2[3]=d2[1];
            d3[0]=sb3[ch0];   d3[1]=sb3[ch0+1];   d3[2]=d3[0];  d3[3]=d3[1];
            dpe[0]=sbias2[ch0]; dpe[1]=sbias2[ch0+1]; dpe[2]=dpe[0]; dpe[3]=dpe[1];

            const int nrow = (nt*8 + tq)*72;
#pragma unroll
            for (int ks = 0; ks < 4; ks++) {
                const int kb = 16*ks + 2*tr;
                unsigned b0, b1;
                b0 = *(const unsigned*)&ws1[nrow + kb];
                b1 = *(const unsigned*)&ws1[nrow + kb + 8];
                mma16816(d1, ax[ks], b0, b1);
                b0 = *(const unsigned*)&ws2[nrow + kb];
                b1 = *(const unsigned*)&ws2[nrow + kb + 8];
                mma16816(d2, ax[ks], b0, b1);
                b0 = *(const unsigned*)&ws3[nrow + kb];
                b1 = *(const unsigned*)&ws3[nrow + kb + 8];
                mma16816(d3, ax[ks], b0, b1);
            }
            const int drow = (nt*8 + tq)*40;
#pragma unroll
            for (int ks = 0; ks < 2; ks++) {
                const int kb = 16*ks + 2*tr;
                unsigned b0 = *(const unsigned*)&dws[drow + kb];
                unsigned b1 = *(const unsigned*)&dws[drow + kb + 8];
                mma16816(dpe, ah[ks], b0, b1);
            }

#pragma unroll
            for (int r = 0; r < 2; r++) {
                const int lpt = ptb + tq + 8*r;
                const int gpt = p0 + lpt;
                float f1a=d1[2*r], f1b=d1[2*r+1];
                float f2a=d2[2*r], f2b=d2[2*r+1];
                float f3a=d3[2*r], f3b=d3[2*r+1];
                float pea=dpe[2*r], peb=dpe[2*r+1];

                uint2 pk;
                pk.x = h2u(__floats2half2_rn(f1a, f1b));
                pk.y = h2u(__floats2half2_rn(f2a, f2b));
                *(uint2*)(g_f12 + (size_t)gpt*128 + 2*ch0) = pk;

                float fo0 = fg[(size_t)(ch0  )*NN + (n0 + lpt)];
                float fo1 = fg[(size_t)(ch0+1)*NN + (n0 + lpt)];
                float bx = fo0 + pea + sscA[ch0  ]*(f2a+f3a) + sshA[ch0  ];
                float by = fo1 + peb + sscA[ch0+1]*(f2b+f3b) + sshA[ch0+1];
                *(float2*)(g_base + (size_t)gpt*CC + ch0) = make_float2(bx, by);
            }
        }
    }
}

// ---------------------------------------------------------------------------
// Kernel 2 (tensor-core MLP): 64 points / block, 512 threads, 2 blocks/SM.
//  A: warp=4 pts, lane=ch-pair -> fp16 gather + hmax2 -> x (fp32 sxs + fp16 xh)
//  B: HMMA h2 = gelu(bnM(mw1 @ x)): warp = (pt-tile w&3, j-block w>>2), 16 MMAs
//  C: HMMA out = x + mw2 @ h2:      warp = (pt-tile w&3, ch-block w>>2), 16 MMAs
// ---------------------------------------------------------------------------
__global__ __launch_bounds__(512, 2) void k2(P2 p) {
    extern __shared__ char smb[];
    float*  sxs  = (float*)smb;                  // 64*68 fp32 x (residual)
    float*  sscM = sxs + 4352;                   // 128
    float*  sshM = sscM + 128;                   // 128  -> 18432 B
    __half* xh   = (__half*)(smb + 18432);       // 64*72   fp16 x
    __half* h2h  = xh + 4608;                    // 64*136  fp16 h2
    __half* w1h  = h2h + 8704;                   // 128*72  mw1 [j][i]
    __half* w2h  = w1h + 9216;                   // 64*136  mw2 [c][j] -> 80896 B

    const int tid = threadIdx.x;
    const int w = tid >> 5, l = tid & 31;

    for (int idx = tid; idx < 8192; idx += 512) {
        int j = idx >> 6, i = idx & 63;
        w1h[j*72 + i] = __float2half(p.mw1[idx]);
    }
    for (int idx = tid; idx < 8192; idx += 512) {
        int c = idx >> 7, j = idx & 127;
        w2h[c*136 + j] = __float2half(p.mw2[idx]);
    }
    if (tid < HID) {
        float sc = p.mg[tid]*rsqrtf(p.mv[tid]+BN_EPS);
        sscM[tid]=sc; sshM[tid]=p.mb[tid]-p.mm[tid]*sc;
    }

    const int p0 = blockIdx.x*64;
    const int b  = p0 >> 14;
    const int n0 = p0 & (NN-1);

    // ---- Phase A: interleaved fp16 gather + edge max ----
    {
        const float sc0 = p.agg_g[2*l  ]*rsqrtf(p.agg_v[2*l  ]+BN_EPS);
        const float sc1 = p.agg_g[2*l+1]*rsqrtf(p.agg_v[2*l+1]+BN_EPS);
        const size_t brow = (size_t)b*NN;
#pragma unroll 1
        for (int i = 0; i < 4; i++) {
            const int lp = w*4 + i;
            const int pt = p0 + lp;
            uint2 cpk = *(const uint2*)(g_f12 + (size_t)pt*128 + 4*l);
            __half2 c1h = *(__half2*)&cpk.x;
            __half2 c2h = *(__half2*)&cpk.y;
            int jreg = 0;
            if (l < KK) jreg = p.qidx[(size_t)pt*KK + l];
            __half2 m1 = __float2half2_rn(-65504.f);
            __half2 m2 = m1;
#pragma unroll
            for (int k = 0; k < KK; k++) {
                int j = __shfl_sync(0xffffffffu, jreg, k);
                uint2 vpk = *(const uint2*)(g_f12 + (brow + (size_t)j)*128 + 4*l);
                m1 = __hmax2(m1, *(__half2*)&vpk.x);
                m2 = __hmax2(m2, *(__half2*)&vpk.y);
            }
            float2 m1f = __half22float2(m1), m2f = __half22float2(m2);
            float2 c1f = __half22float2(c1h), c2f = __half22float2(c2h);
            float e0 = (m1f.x - c1f.x) + (m2f.x - c2f.x);
            float e1 = (m1f.y - c1f.y) + (m2f.y - c2f.y);
            float2 bs = *(const float2*)(g_base + (size_t)pt*CC + 2*l);
            float v0 = bs.x + sc0*e0;
            float v1 = bs.y + sc1*e1;
            sxs[lp*68 + 2*l  ] = v0;
            sxs[lp*68 + 2*l+1] = v1;
            *(unsigned*)&xh[lp*72 + 2*l] = h2u(__floats2half2_rn(v0, v1));
        }
    }
    __syncthreads();

    const int tq = l >> 2, tr = l & 3;

    // ---- Phase B: h2 = gelu(bnM(mw1 @ x)) via HMMA ----
    {
        const int pw = w & 3;           // point tile (16 pts)
        const int nb = w >> 2;          // j block (32 j's)
        const int ptb = pw*16;
        unsigned ax[4][4];
#pragma unroll
        for (int ks = 0; ks < 4; ks++) {
            int r0 = (ptb + tq)*72, r1 = r0 + 8*72;
            int k0 = 16*ks + 2*tr;
            ax[ks][0] = *(const unsigned*)&xh[r0 + k0];
            ax[ks][1] = *(const unsigned*)&xh[r1 + k0];
            ax[ks][2] = *(const unsigned*)&xh[r0 + k0 + 8];
            ax[ks][3] = *(const unsigned*)&xh[r1 + k0 + 8];
        }
#pragma unroll
        for (int nt = 0; nt < 4; nt++) {
            const int jr = nb*32 + nt*8;
            float d[4] = {0.f,0.f,0.f,0.f};
            const int nrow = (jr + tq)*72;
#pragma unroll
            for (int ks = 0; ks < 4; ks++) {
                const int kb = 16*ks + 2*tr;
                unsigned b0 = *(const unsigned*)&w1h[nrow + kb];
                unsigned b1 = *(const unsigned*)&w1h[nrow + kb + 8];
                mma16816(d, ax[ks], b0, b1);
            }
            const int j0 = jr + 2*tr;
            float sc0 = sscM[j0], sh0 = sshM[j0];
            float sc1 = sscM[j0+1], sh1 = sshM[j0+1];
            float g0 = gelu_exact(d[0]*sc0 + sh0);
            float g1 = gelu_exact(d[1]*sc1 + sh1);
            float g2 = gelu_exact(d[2]*sc0 + sh0);
            float g3 = gelu_exact(d[3]*sc1 + sh1);
            *(unsigned*)&h2h[(ptb+tq  )*136 + j0] = h2u(__floats2half2_rn(g0, g1));
            *(unsigned*)&h2h[(ptb+tq+8)*136 + j0] = h2u(__floats2half2_rn(g2, g3));
        }
    }
    __syncthreads();

    // ---- Phase C: out = x + mw2 @ h2 via HMMA ----
    {
        const int pw = w & 3;           // point tile
        const int cb = w >> 2;          // channel block (16 ch)
        const int ptb = pw*16;
        const size_t obase = (size_t)b*CC*NN;
#pragma unroll
        for (int nt = 0; nt < 2; nt++) {
            const int ch = cb*16 + nt*8;
            float d[4] = {0.f,0.f,0.f,0.f};
            const int nrow = (ch + tq)*136;
#pragma unroll
            for (int ks = 0; ks < 8; ks++) {
                const int k0 = 16*ks + 2*tr;
                unsigned a[4];
                int r0 = (ptb + tq)*136, r1 = r0 + 8*136;
                a[0] = *(const unsigned*)&h2h[r0 + k0];
                a[1] = *(const unsigned*)&h2h[r1 + k0];
                a[2] = *(const unsigned*)&h2h[r0 + k0 + 8];
                a[3] = *(const unsigned*)&h2h[r1 + k0 + 8];
                unsigned b0 = *(const unsigned*)&w2h[nrow + k0];
                unsigned b1 = *(const unsigned*)&w2h[nrow + k0 + 8];
                mma16816(d, a, b0, b1);
            }
            const int c0 = ch + 2*tr;
            float x00 = sxs[(ptb+tq  )*68 + c0];
            float x01 = sxs[(ptb+tq  )*68 + c0+1];
            float x10 = sxs[(ptb+tq+8)*68 + c0];
            float x11 = sxs[(ptb+tq+8)*68 + c0+1];
            p.out[obase + (size_t)(c0  )*NN + n0 + ptb+tq  ] = x00 + d[0];
            p.out[obase + (size_t)(c0+1)*NN + n0 + ptb+tq  ] = x01 + d[1];
            p.out[obase + (size_t)(c0  )*NN + n0 + ptb+tq+8] = x10 + d[2];
            p.out[obase + (size_t)(c0+1)*NN + n0 + ptb+tq+8] = x11 + d[3];
        }
    }
}

// ---------------------------------------------------------------------------
extern "C" void kernel_launch(void* const* d_in, const int* in_sizes, int n_in,
                              void* d_out, int out_size) {
    const float* f        = (const float*)d_in[0];
    const float* dp       = (const float*)d_in[1];
    const int*   qidx     = (const int*)  d_in[2];
    const float* dirv     = (const float*)d_in[3];
    const float* de_w1    = (const float*)d_in[4];
    const float* de_g1    = (const float*)d_in[5];
    const float* de_b1    = (const float*)d_in[6];
    const float* de_m1    = (const float*)d_in[7];
    const float* de_v1    = (const float*)d_in[8];
    const float* de_w2    = (const float*)d_in[9];
    const float* de_bias2 = (const float*)d_in[10];
    const float* w1       = (const float*)d_in[11];
    const float* b1       = (const float*)d_in[12];
    const float* w2       = (const float*)d_in[13];
    const float* b2       = (const float*)d_in[14];
    const float* w3       = (const float*)d_in[15];
    const float* b3       = (const float*)d_in[16];
    const float* agg_g    = (const float*)d_in[17];
    const float* agg_b    = (const float*)d_in[18];
    const float* agg_m    = (const float*)d_in[19];
    const float* agg_v    = (const float*)d_in[20];
    const float* mw1      = (const float*)d_in[21];
    const float* mg       = (const float*)d_in[22];
    const float* mb       = (const float*)d_in[23];
    const float* mm       = (const float*)d_in[24];
    const float* mv       = (const float*)d_in[25];
    const float* mw2      = (const float*)d_in[26];

    P1 p1;
    p1.f=f; p1.dp=dp; p1.dirv=dirv;
    p1.de_w1=de_w1; p1.de_g1=de_g1; p1.de_b1=de_b1; p1.de_m1=de_m1; p1.de_v1=de_v1;
    p1.de_w2=de_w2; p1.de_bias2=de_bias2;
    p1.w1=w1; p1.b1=b1; p1.w2=w2; p1.b2=b2; p1.w3=w3; p1.b3=b3;
    p1.agg_g=agg_g; p1.agg_b=agg_b; p1.agg_m=agg_m; p1.agg_v=agg_v;

    P2 p2;
    p2.qidx=qidx; p2.agg_g=agg_g; p2.agg_v=agg_v;
    p2.mw1=mw1; p2.mg=mg; p2.mb=mb; p2.mm=mm; p2.mv=mv; p2.mw2=mw2;
    p2.out=(float*)d_out;

    const size_t smem1 = 96512;   // bytes
    const size_t smem2 = 80896;   // bytes
    cudaFuncSetAttribute(k1, cudaFuncAttributeMaxDynamicSharedMemorySize, (int)smem1);
    cudaFuncSetAttribute(k2, cudaFuncAttributeMaxDynamicSharedMemorySize, (int)smem2);

    k1<<<NPTS/256, 256, smem1>>>(p1);
    k2<<<NPTS/64, 512, smem2>>>(p2);
}

// round 8
// speedup vs baseline: 2.5189x; 1.0022x over previous
#include <cuda_runtime.h>
#include <cuda_fp16.h>
#include <math.h>

// Problem constants
#define BB   8
#define NN   16384
#define KK   16
#define CC   64
#define MM   32
#define HH   32
#define HID  128
#define NPTS (BB*NN)          // 131072
#define BN_EPS 1e-5f

typedef unsigned long long u64;

__device__ __forceinline__ float gelu_exact(float y) {
    return 0.5f * y * (1.0f + erff(y * 0.70710678118654752f));
}

__device__ __forceinline__ unsigned h2u(__half2 h) { return *(unsigned*)&h; }

// m16n8k16 fp16 MMA, fp32 accumulate
__device__ __forceinline__ void mma16816(float d[4], const unsigned a[4],
                                         unsigned b0, unsigned b1) {
    asm volatile("mma.sync.aligned.m16n8k16.row.col.f32.f16.f16.f32 "
        "{%0,%1,%2,%3}, {%4,%5,%6,%7}, {%8,%9}, {%0,%1,%2,%3};"
        : "+f"(d[0]), "+f"(d[1]), "+f"(d[2]), "+f"(d[3])
        : "r"(a[0]), "r"(a[1]), "r"(a[2]), "r"(a[3]), "r"(b0), "r"(b1));
}

// Scratch: interleaved fp16 rows per point: [{f1[2c],f1[2c+1],f2[2c],f2[2c+1]} c=0..31]
__device__ __half g_f12[(size_t)NPTS*128];
__device__ float  g_base[(size_t)NPTS*CC];

struct P1 {
    const float *f, *dp, *dirv;
    const float *de_w1, *de_g1, *de_b1, *de_m1, *de_v1, *de_w2, *de_bias2;
    const float *w1, *b1, *w2, *b2, *w3, *b3;
    const float *agg_g, *agg_b, *agg_m, *agg_v;
};

struct P2 {
    const int*   qidx;
    const float *agg_g, *agg_v;
    const float *mw1, *mg, *mb, *mm, *mv, *mw2;
    float* out;
};

// ---------------------------------------------------------------------------
// Kernel 1 (tensor-core, unchanged from R7): 256 threads, 256 points / block.
// ---------------------------------------------------------------------------
__global__ __launch_bounds__(256) void k1(P1 p) {
    extern __shared__ char smbase[];
    float* sdw1   = (float*)smbase;            // 1024  de_w1 [32j][32m]
    float* svv    = sdw1 + 1024;               // 128
    float* sb1    = svv  + 128;                // 64
    float* sb2    = sb1  + 64;
    float* sb3    = sb2  + 64;
    float* sbias2 = sb3  + 64;                 // 64
    float* ssc1   = sbias2 + 64;               // 32
    float* ssh1   = ssc1 + 32;                 // 32
    float* sscA   = ssh1 + 32;                 // 64
    float* sshA   = sscA + 64;                 // 64 -> 1600 floats (6400 B)
    __half* xA  = (__half*)(smbase + 6400);    // 256*72
    __half* hA  = xA  + 18432;                 // 256*40
    __half* ws1 = hA  + 10240;                 // 64*72
    __half* ws2 = ws1 + 4608;
    __half* ws3 = ws2 + 4608;
    __half* dws = ws3 + 4608;                  // 64*40 -> total 96512 B

    const int tid = threadIdx.x;

    for (int idx = tid; idx < 4096; idx += 256) {
        int c = idx >> 6, i = idx & 63;
        ws1[c*72+i] = __float2half(p.w1[idx]);
        ws2[c*72+i] = __float2half(p.w2[idx]);
        ws3[c*72+i] = __float2half(p.w3[idx]);
    }
    for (int idx = tid; idx < 2048; idx += 256) {
        int c = idx >> 5, h = idx & 31;
        dws[c*40+h] = __float2half(p.de_w2[idx]);
    }
    for (int i = tid; i < 1024; i += 256) sdw1[i] = p.de_w1[i];
    if (tid < 64) {
        sb1[tid]=p.b1[tid]; sb2[tid]=p.b2[tid]; sb3[tid]=p.b3[tid];
        sbias2[tid]=p.de_bias2[tid];
        float sc = p.agg_g[tid]*rsqrtf(p.agg_v[tid]+BN_EPS);
        sscA[tid]=sc; sshA[tid]=p.agg_b[tid]-p.agg_m[tid]*sc;
    }
    if (tid < 32) {
        float v0=p.dirv[tid*3+0], v1=p.dirv[tid*3+1], v2=p.dirv[tid*3+2];
        float inv = rsqrtf(fmaxf(v0*v0+v1*v1+v2*v2, 1e-24f));
        svv[tid*4+0]=v0*inv; svv[tid*4+1]=v1*inv; svv[tid*4+2]=v2*inv; svv[tid*4+3]=0.f;
        float sc = p.de_g1[tid]*rsqrtf(p.de_v1[tid]+BN_EPS);
        ssc1[tid]=sc; ssh1[tid]=p.de_b1[tid]-p.de_m1[tid]*sc;
    }
    __syncthreads();

    const int p0 = blockIdx.x*256;
    const int b  = p0 >> 14;
    const int n0 = p0 & (NN-1);
    const int n  = n0 + tid;

    // ---- theta_max (thread = point) ----
    {
        float xn0[KK], xn1[KK], xn2[KK];
        const float4* dp4 = (const float4*)(p.dp + (size_t)b*3*NN*KK + (size_t)n*KK);
#pragma unroll
        for (int k4 = 0; k4 < 4; k4++) {
            float4 A = dp4[k4];
            float4 Bv= dp4[(NN*KK/4) + k4];
            float4 Cv= dp4[(2*NN*KK/4) + k4];
            float ax[4]={A.x,A.y,A.z,A.w}, bx[4]={Bv.x,Bv.y,Bv.z,Bv.w}, cx[4]={Cv.x,Cv.y,Cv.z,Cv.w};
#pragma unroll
            for (int kk = 0; kk < 4; kk++) {
                float x0=ax[kk], x1=bx[kk], x2=cx[kk];
                float inv = rsqrtf(fmaxf(x0*x0+x1*x1+x2*x2, 1e-24f));
                xn0[4*k4+kk]=x0*inv; xn1[4*k4+kk]=x1*inv; xn2[4*k4+kk]=x2*inv;
            }
        }
        float tm[MM];
        const float4* sv4 = (const float4*)svv;
#pragma unroll
        for (int m = 0; m < MM; m++) {
            float4 v = sv4[m];
            float acc = -INFINITY;
#pragma unroll
            for (int k = 0; k < KK; k++)
                acc = fmaxf(acc, v.x*xn0[k] + v.y*xn1[k] + v.z*xn2[k]);
            tm[m] = acc;
        }
        const float4* sdw1_4 = (const float4*)sdw1;
#pragma unroll
        for (int j2 = 0; j2 < HH/2; j2++) {
            float hv[2];
#pragma unroll
            for (int q = 0; q < 2; q++) {
                int j = 2*j2 + q;
                float acc = 0.f;
#pragma unroll
                for (int m4 = 0; m4 < 8; m4++) {
                    float4 w = sdw1_4[j*8 + m4];
                    acc += w.x*tm[4*m4] + w.y*tm[4*m4+1] + w.z*tm[4*m4+2] + w.w*tm[4*m4+3];
                }
                hv[q] = gelu_exact(acc*ssc1[j] + ssh1[j]);
            }
            *(unsigned*)&hA[tid*40 + 2*j2] = h2u(__floats2half2_rn(hv[0], hv[1]));
        }
    }

    // ---- stage x tile ----
    {
        const float* fb = p.f + (size_t)b*CC*NN + n;
#pragma unroll
        for (int c2 = 0; c2 < 32; c2++) {
            float v0 = fb[(size_t)(2*c2  )*NN];
            float v1 = fb[(size_t)(2*c2+1)*NN];
            *(unsigned*)&xA[tid*72 + 2*c2] = h2u(__floats2half2_rn(v0, v1));
        }
    }
    __syncthreads();

    const int w  = tid >> 5;
    const int lt = tid & 31;
    const int tq = lt >> 2;
    const int tr = lt & 3;
    const float* fg = p.f + (size_t)b*CC*NN;

#pragma unroll 1
    for (int pti = 0; pti < 2; pti++) {
        const int ptb = (w*2 + pti) * 16;
        unsigned ax[4][4], ah[2][4];
#pragma unroll
        for (int ks = 0; ks < 4; ks++) {
            int r0 = (ptb + tq)*72, r1 = r0 + 8*72;
            int k0 = 16*ks + 2*tr;
            ax[ks][0] = *(const unsigned*)&xA[r0 + k0];
            ax[ks][1] = *(const unsigned*)&xA[r1 + k0];
            ax[ks][2] = *(const unsigned*)&xA[r0 + k0 + 8];
            ax[ks][3] = *(const unsigned*)&xA[r1 + k0 + 8];
        }
#pragma unroll
        for (int ks = 0; ks < 2; ks++) {
            int r0 = (ptb + tq)*40, r1 = r0 + 8*40;
            int k0 = 16*ks + 2*tr;
            ah[ks][0] = *(const unsigned*)&hA[r0 + k0];
            ah[ks][1] = *(const unsigned*)&hA[r1 + k0];
            ah[ks][2] = *(const unsigned*)&hA[r0 + k0 + 8];
            ah[ks][3] = *(const unsigned*)&hA[r1 + k0 + 8];
        }

#pragma unroll 1
        for (int nt = 0; nt < 8; nt++) {
            const int ch0 = nt*8 + tr*2;
            float d1[4], d2[4], d3[4], dpe[4];
            d1[0]=sb1[ch0];   d1[1]=sb1[ch0+1];   d1[2]=d1[0];  d1[3]=d1[1];
            d2[0]=sb2[ch0];   d2[1]=sb2[ch0+1];   d2[2]=d2[0];  d2[3]=d2[1];
            d3[0]=sb3[ch0];   d3[1]=sb3[ch0+1];   d3[2]=d3[0];  d3[3]=d3[1];
            dpe[0]=sbias2[ch0]; dpe[1]=sbias2[ch0+1]; dpe[2]=dpe[0]; dpe[3]=dpe[1];

            const int nrow = (nt*8 + tq)*72;
#pragma unroll
            for (int ks = 0; ks < 4; ks++) {
                const int kb = 16*ks + 2*tr;
                unsigned b0, b1;
                b0 = *(const unsigned*)&ws1[nrow + kb];
                b1 = *(const unsigned*)&ws1[nrow + kb + 8];
                mma16816(d1, ax[ks], b0, b1);
                b0 = *(const unsigned*)&ws2[nrow + kb];
                b1 = *(const unsigned*)&ws2[nrow + kb + 8];
                mma16816(d2, ax[ks], b0, b1);
                b0 = *(const unsigned*)&ws3[nrow + kb];
                b1 = *(const unsigned*)&ws3[nrow + kb + 8];
                mma16816(d3, ax[ks], b0, b1);
            }
            const int drow = (nt*8 + tq)*40;
#pragma unroll
            for (int ks = 0; ks < 2; ks++) {
                const int kb = 16*ks + 2*tr;
                unsigned b0 = *(const unsigned*)&dws[drow + kb];
                unsigned b1 = *(const unsigned*)&dws[drow + kb + 8];
                mma16816(dpe, ah[ks], b0, b1);
            }

#pragma unroll
            for (int r = 0; r < 2; r++) {
                const int lpt = ptb + tq + 8*r;
                const int gpt = p0 + lpt;
                float f1a=d1[2*r], f1b=d1[2*r+1];
                float f2a=d2[2*r], f2b=d2[2*r+1];
                float f3a=d3[2*r], f3b=d3[2*r+1];
                float pea=dpe[2*r], peb=dpe[2*r+1];

                uint2 pk;
                pk.x = h2u(__floats2half2_rn(f1a, f1b));
                pk.y = h2u(__floats2half2_rn(f2a, f2b));
                *(uint2*)(g_f12 + (size_t)gpt*128 + 2*ch0) = pk;

                float fo0 = fg[(size_t)(ch0  )*NN + (n0 + lpt)];
                float fo1 = fg[(size_t)(ch0+1)*NN + (n0 + lpt)];
                float bx = fo0 + pea + sscA[ch0  ]*(f2a+f3a) + sshA[ch0  ];
                float by = fo1 + peb + sscA[ch0+1]*(f2b+f3b) + sshA[ch0+1];
                *(float2*)(g_base + (size_t)gpt*CC + ch0) = make_float2(bx, by);
            }
        }
    }
}

// ---------------------------------------------------------------------------
// Kernel 2: 64 points / block, 512 threads, 2 blocks/SM.
//  A: paired-point LDG.128 gather — lanes 0-15 = point A, 16-31 = point B,
//     lane chunk = 16B of the interleaved f1/f2 row (4 channels)
//  B: HMMA h2 = gelu(bnM(mw1 @ x))
//  C: HMMA out = x + mw2 @ h2
// ---------------------------------------------------------------------------
__global__ __launch_bounds__(512, 2) void k2(P2 p) {
    extern __shared__ char smb[];
    float*  sxs  = (float*)smb;                  // 64*68 fp32 x (residual)
    float*  sscM = sxs + 4352;                   // 128
    float*  sshM = sscM + 128;                   // 128
    float*  sA   = sshM + 128;                   // 64 folded agg scale -> 18688 B
    __half* xh   = (__half*)(smb + 18688);       // 64*72   fp16 x
    __half* h2h  = xh + 4608;                    // 64*136  fp16 h2
    __half* w1h  = h2h + 8704;                   // 128*72  mw1 [j][i]
    __half* w2h  = w1h + 9216;                   // 64*136  mw2 [c][j] -> 81152 B

    const int tid = threadIdx.x;
    const int w = tid >> 5, l = tid & 31;

    for (int idx = tid; idx < 8192; idx += 512) {
        int j = idx >> 6, i = idx & 63;
        w1h[j*72 + i] = __float2half(p.mw1[idx]);
    }
    for (int idx = tid; idx < 8192; idx += 512) {
        int c = idx >> 7, j = idx & 127;
        w2h[c*136 + j] = __float2half(p.mw2[idx]);
    }
    if (tid < HID) {
        float sc = p.mg[tid]*rsqrtf(p.mv[tid]+BN_EPS);
        sscM[tid]=sc; sshM[tid]=p.mb[tid]-p.mm[tid]*sc;
    }
    if (tid < CC) {
        sA[tid] = p.agg_g[tid]*rsqrtf(p.agg_v[tid]+BN_EPS);
    }
    __syncthreads();

    const int p0 = blockIdx.x*64;
    const int b  = p0 >> 14;
    const int n0 = p0 & (NN-1);

    // ---- Phase A: paired-point gather + edge max ----
    {
        const int half = (l >> 4) & 1;
        const int c    = l & 15;
        const size_t brow = (size_t)b*NN;
        const __half2 NEG = __float2half2_rn(-65504.f);
#pragma unroll 1
        for (int i = 0; i < 2; i++) {
            const int lpA = w*4 + 2*i;
            const int lp  = lpA + half;
            const int pt  = p0 + lp;
            int jreg = p.qidx[(size_t)(p0 + lpA)*KK + l];   // covers both points
            __half2 m1a = NEG, m2a = NEG, m1b = NEG, m2b = NEG;
#pragma unroll
            for (int r = 0; r < KK; r++) {
                int j = __shfl_sync(0xffffffffu, jreg, (l & 16) + r);
                uint4 v = *(const uint4*)(g_f12 + ((brow + (size_t)j) << 7) + c*8);
                m1a = __hmax2(m1a, *(__half2*)&v.x);
                m2a = __hmax2(m2a, *(__half2*)&v.y);
                m1b = __hmax2(m1b, *(__half2*)&v.z);
                m2b = __hmax2(m2b, *(__half2*)&v.w);
            }
            uint4 cv = *(const uint4*)(g_f12 + ((size_t)pt << 7) + c*8);
            float2 c1a = __half22float2(*(__half2*)&cv.x);
            float2 c2a = __half22float2(*(__half2*)&cv.y);
            float2 c1b = __half22float2(*(__half2*)&cv.z);
            float2 c2b = __half22float2(*(__half2*)&cv.w);
            float2 M1a = __half22float2(m1a), M2a = __half22float2(m2a);
            float2 M1b = __half22float2(m1b), M2b = __half22float2(m2b);
            float4 bs = *(const float4*)(g_base + (size_t)pt*CC + 4*c);
            float4 sc = *(const float4*)&sA[4*c];
            float v0 = bs.x + sc.x*((M1a.x - c1a.x) + (M2a.x - c2a.x));
            float v1 = bs.y + sc.y*((M1a.y - c1a.y) + (M2a.y - c2a.y));
            float v2 = bs.z + sc.z*((M1b.x - c1b.x) + (M2b.x - c2b.x));
            float v3 = bs.w + sc.w*((M1b.y - c1b.y) + (M2b.y - c2b.y));
            *(float4*)&sxs[lp*68 + 4*c] = make_float4(v0,v1,v2,v3);
            uint2 xp;
            xp.x = h2u(__floats2half2_rn(v0, v1));
            xp.y = h2u(__floats2half2_rn(v2, v3));
            *(uint2*)&xh[lp*72 + 4*c] = xp;
        }
    }
    __syncthreads();

    const int tq = l >> 2, tr = l & 3;

    // ---- Phase B: h2 = gelu(bnM(mw1 @ x)) via HMMA ----
    {
        const int pw = w & 3;           // point tile (16 pts)
        const int nb = w >> 2;          // j block (32 j's)
        const int ptb = pw*16;
        unsigned ax[4][4];
#pragma unroll
        for (int ks = 0; ks < 4; ks++) {
            int r0 = (ptb + tq)*72, r1 = r0 + 8*72;
            int k0 = 16*ks + 2*tr;
            ax[ks][0] = *(const unsigned*)&xh[r0 + k0];
            ax[ks][1] = *(const unsigned*)&xh[r1 + k0];
            ax[ks][2] = *(const unsigned*)&xh[r0 + k0 + 8];
            ax[ks][3] = *(const unsigned*)&xh[r1 + k0 + 8];
        }
#pragma unroll
        for (int nt = 0; nt < 4; nt++) {
            const int jr = nb*32 + nt*8;
            float d[4] = {0.f,0.f,0.f,0.f};
            const int nrow = (jr + tq)*72;
#pragma unroll
            for (int ks = 0; ks < 4; ks++) {
                const int kb = 16*ks + 2*tr;
                unsigned b0 = *(const unsigned*)&w1h[nrow + kb];
                unsigned b1 = *(const unsigned*)&w1h[nrow + kb + 8];
                mma16816(d, ax[ks], b0, b1);
            }
            const int j0 = jr + 2*tr;
            float sc0 = sscM[j0], sh0 = sshM[j0];
            float sc1 = sscM[j0+1], sh1 = sshM[j0+1];
            float g0 = gelu_exact(d[0]*sc0 + sh0);
            float g1 = gelu_exact(d[1]*sc1 + sh1);
            float g2 = gelu_exact(d[2]*sc0 + sh0);
            float g3 = gelu_exact(d[3]*sc1 + sh1);
            *(unsigned*)&h2h[(ptb+tq  )*136 + j0] = h2u(__floats2half2_rn(g0, g1));
            *(unsigned*)&h2h[(ptb+tq+8)*136 + j0] = h2u(__floats2half2_rn(g2, g3));
        }
    }
    __syncthreads();

    // ---- Phase C: out = x + mw2 @ h2 via HMMA ----
    {
        const int pw = w & 3;           // point tile
        const int cb = w >> 2;          // channel block (16 ch)
        const int ptb = pw*16;
        const size_t obase = (size_t)b*CC*NN;
#pragma unroll
        for (int nt = 0; nt < 2; nt++) {
            const int ch = cb*16 + nt*8;
            float d[4] = {0.f,0.f,0.f,0.f};
            const int nrow = (ch + tq)*136;
#pragma unroll
            for (int ks = 0; ks < 8; ks++) {
                const int k0 = 16*ks + 2*tr;
                unsigned a[4];
                int r0 = (ptb + tq)*136, r1 = r0 + 8*136;
                a[0] = *(const unsigned*)&h2h[r0 + k0];
                a[1] = *(const unsigned*)&h2h[r1 + k0];
                a[2] = *(const unsigned*)&h2h[r0 + k0 + 8];
                a[3] = *(const unsigned*)&h2h[r1 + k0 + 8];
                unsigned b0 = *(const unsigned*)&w2h[nrow + k0];
                unsigned b1 = *(const unsigned*)&w2h[nrow + k0 + 8];
                mma16816(d, a, b0, b1);
            }
            const int c0 = ch + 2*tr;
            float x00 = sxs[(ptb+tq  )*68 + c0];
            float x01 = sxs[(ptb+tq  )*68 + c0+1];
            float x10 = sxs[(ptb+tq+8)*68 + c0];
            float x11 = sxs[(ptb+tq+8)*68 + c0+1];
            p.out[obase + (size_t)(c0  )*NN + n0 + ptb+tq  ] = x00 + d[0];
            p.out[obase + (size_t)(c0+1)*NN + n0 + ptb+tq  ] = x01 + d[1];
            p.out[obase + (size_t)(c0  )*NN + n0 + ptb+tq+8] = x10 + d[2];
            p.out[obase + (size_t)(c0+1)*NN + n0 + ptb+tq+8] = x11 + d[3];
        }
    }
}

// ---------------------------------------------------------------------------
extern "C" void kernel_launch(void* const* d_in, const int* in_sizes, int n_in,
                              void* d_out, int out_size) {
    const float* f        = (const float*)d_in[0];
    const float* dp       = (const float*)d_in[1];
    const int*   qidx     = (const int*)  d_in[2];
    const float* dirv     = (const float*)d_in[3];
    const float* de_w1    = (const float*)d_in[4];
    const float* de_g1    = (const float*)d_in[5];
    const float* de_b1    = (const float*)d_in[6];
    const float* de_m1    = (const float*)d_in[7];
    const float* de_v1    = (const float*)d_in[8];
    const float* de_w2    = (const float*)d_in[9];
    const float* de_bias2 = (const float*)d_in[10];
    const float* w1       = (const float*)d_in[11];
    const float* b1       = (const float*)d_in[12];
    const float* w2       = (const float*)d_in[13];
    const float* b2       = (const float*)d_in[14];
    const float* w3       = (const float*)d_in[15];
    const float* b3       = (const float*)d_in[16];
    const float* agg_g    = (const float*)d_in[17];
    const float* agg_b    = (const float*)d_in[18];
    const float* agg_m    = (const float*)d_in[19];
    const float* agg_v    = (const float*)d_in[20];
    const float* mw1      = (const float*)d_in[21];
    const float* mg       = (const float*)d_in[22];
    const float* mb       = (const float*)d_in[23];
    const float* mm       = (const float*)d_in[24];
    const float* mv       = (const float*)d_in[25];
    const float* mw2      = (const float*)d_in[26];

    P1 p1;
    p1.f=f; p1.dp=dp; p1.dirv=dirv;
    p1.de_w1=de_w1; p1.de_g1=de_g1; p1.de_b1=de_b1; p1.de_m1=de_m1; p1.de_v1=de_v1;
    p1.de_w2=de_w2; p1.de_bias2=de_bias2;
    p1.w1=w1; p1.b1=b1; p1.w2=w2; p1.b2=b2; p1.w3=w3; p1.b3=b3;
    p1.agg_g=agg_g; p1.agg_b=agg_b; p1.agg_m=agg_m; p1.agg_v=agg_v;

    P2 p2;
    p2.qidx=qidx; p2.agg_g=agg_g; p2.agg_v=agg_v;
    p2.mw1=mw1; p2.mg=mg; p2.mb=mb; p2.mm=mm; p2.mv=mv; p2.mw2=mw2;
    p2.out=(float*)d_out;

    const size_t smem1 = 96512;   // bytes
    const size_t smem2 = 81152;   // bytes
    cudaFuncSetAttribute(k1, cudaFuncAttributeMaxDynamicSharedMemorySize, (int)smem1);
    cudaFuncSetAttribute(k2, cudaFuncAttributeMaxDynamicSharedMemorySize, (int)smem2);

    k1<<<NPTS/256, 256, smem1>>>(p1);
    k2<<<NPTS/64, 512, smem2>>>(p2);
}

// round 9
// speedup vs baseline: 3.8075x; 1.5115x over previous
#include <cuda_runtime.h>
#include <cuda_fp16.h>
#include <math.h>

// Problem constants
#define BB   8
#define NN   16384
#define KK   16
#define CC   64
#define MM   32
#define HH   32
#define HID  128
#define NPTS (BB*NN)          // 131072
#define BN_EPS 1e-5f

typedef unsigned long long u64;

__device__ __forceinline__ float gelu_exact(float y) {
    return 0.5f * y * (1.0f + erff(y * 0.70710678118654752f));
}

__device__ __forceinline__ unsigned h2u(__half2 h) { return *(unsigned*)&h; }

// m16n8k16 fp16 MMA, fp32 accumulate
__device__ __forceinline__ void mma16816(float d[4], const unsigned a[4],
                                         unsigned b0, unsigned b1) {
    asm volatile("mma.sync.aligned.m16n8k16.row.col.f32.f16.f16.f32 "
        "{%0,%1,%2,%3}, {%4,%5,%6,%7}, {%8,%9}, {%0,%1,%2,%3};"
        : "+f"(d[0]), "+f"(d[1]), "+f"(d[2]), "+f"(d[3])
        : "r"(a[0]), "r"(a[1]), "r"(a[2]), "r"(a[3]), "r"(b0), "r"(b1));
}

// Scratch
__device__ __half g_f12[(size_t)NPTS*128];
__device__ float  g_base[(size_t)NPTS*CC];

// Pre-converted weights (fp16, padded smem-image layouts) + folded params
__device__ __half g_k1w[16384];   // [ws1 4608][ws2 4608][ws3 4608][dws 2560]
__device__ __half g_k2w[17920];   // [w1h 9216 (pitch 72)][w2h 8704 (pitch 136)]
__device__ float  g_par1[1600];   // [sdw1 1024][svv 128][sb1 64][sb2 64][sb3 64][sbias2 64][ssc1 32][ssh1 32][sscA 64][sshA 64]
__device__ float  g_par2[320];    // [sscM 128][sshM 128][sA 64]

struct P0 {
    const float *dirv, *de_w1, *de_g1, *de_b1, *de_m1, *de_v1, *de_w2, *de_bias2;
    const float *w1, *b1, *w2, *b2, *w3, *b3;
    const float *agg_g, *agg_b, *agg_m, *agg_v;
    const float *mw1, *mg, *mb, *mm, *mv, *mw2;
};

struct P1 {
    const float *f, *dp;
};

struct P2 {
    const int* qidx;
    float* out;
};

// ---------------------------------------------------------------------------
// Kernel 0: one-time weight conversion + BN folding (graph-captured each run).
// ---------------------------------------------------------------------------
__global__ void k0(P0 p) {
    const int tid = blockIdx.x*blockDim.x + threadIdx.x;
    const int stride = gridDim.x*blockDim.x;
    for (int idx = tid; idx < 4096; idx += stride) {
        int c = idx >> 6, i = idx & 63;
        g_k1w[c*72+i]         = __float2half(p.w1[idx]);
        g_k1w[4608 + c*72+i]  = __float2half(p.w2[idx]);
        g_k1w[9216 + c*72+i]  = __float2half(p.w3[idx]);
    }
    for (int idx = tid; idx < 2048; idx += stride) {
        int c = idx >> 5, h = idx & 31;
        g_k1w[13824 + c*40+h] = __float2half(p.de_w2[idx]);
    }
    for (int idx = tid; idx < 8192; idx += stride) {
        int j = idx >> 6, i = idx & 63;
        g_k2w[j*72 + i] = __float2half(p.mw1[idx]);
    }
    for (int idx = tid; idx < 8192; idx += stride) {
        int c = idx >> 7, j = idx & 127;
        g_k2w[9216 + c*136 + j] = __float2half(p.mw2[idx]);
    }
    for (int i = tid; i < 1024; i += stride) g_par1[i] = p.de_w1[i];
    if (tid < 32) {
        float v0=p.dirv[tid*3+0], v1=p.dirv[tid*3+1], v2=p.dirv[tid*3+2];
        float inv = rsqrtf(fmaxf(v0*v0+v1*v1+v2*v2, 1e-24f));
        g_par1[1024+tid*4+0]=v0*inv; g_par1[1024+tid*4+1]=v1*inv;
        g_par1[1024+tid*4+2]=v2*inv; g_par1[1024+tid*4+3]=0.f;
        float sc = p.de_g1[tid]*rsqrtf(p.de_v1[tid]+BN_EPS);
        g_par1[1408+tid]=sc;
        g_par1[1440+tid]=p.de_b1[tid]-p.de_m1[tid]*sc;
    }
    if (tid >= 32 && tid < 96) {
        int c = tid - 32;
        g_par1[1152+c]=p.b1[c];
        g_par1[1216+c]=p.b2[c];
        g_par1[1280+c]=p.b3[c];
        g_par1[1344+c]=p.de_bias2[c];
        float sc = p.agg_g[c]*rsqrtf(p.agg_v[c]+BN_EPS);
        g_par1[1472+c]=sc;
        g_par1[1536+c]=p.agg_b[c]-p.agg_m[c]*sc;
        g_par2[256+c]=sc;
    }
    if (tid >= 96 && tid < 224) {
        int j = tid - 96;
        float sc = p.mg[j]*rsqrtf(p.mv[j]+BN_EPS);
        g_par2[j]=sc;
        g_par2[128+j]=p.mb[j]-p.mm[j]*sc;
    }
}

// ---------------------------------------------------------------------------
// Kernel 1 (tensor-core): 256 threads, 256 points / block.
// ---------------------------------------------------------------------------
__global__ __launch_bounds__(256) void k1(P1 p) {
    extern __shared__ char smbase[];
    float* sdw1   = (float*)smbase;            // 1024
    float* svv    = sdw1 + 1024;               // 128
    float* sb1    = svv  + 128;                // 64
    float* sb2    = sb1  + 64;
    float* sb3    = sb2  + 64;
    float* sbias2 = sb3  + 64;                 // 64
    float* ssc1   = sbias2 + 64;               // 32
    float* ssh1   = ssc1 + 32;                 // 32
    float* sscA   = ssh1 + 32;                 // 64
    float* sshA   = sscA + 64;                 // 64 -> 1600 floats (6400 B)
    __half* xA  = (__half*)(smbase + 6400);    // 256*72
    __half* hA  = xA  + 18432;                 // 256*40
    __half* ws1 = hA  + 10240;                 // 64*72 (then ws2, ws3, dws contiguous)
    __half* ws2 = ws1 + 4608;
    __half* ws3 = ws2 + 4608;
    __half* dws = ws3 + 4608;                  // -> total 96512 B

    const int tid = threadIdx.x;

    // fast staging: weights (uint4) + params (float4) from preconverted globals
    {
        const uint4* src = (const uint4*)g_k1w;
        uint4* dst = (uint4*)ws1;
#pragma unroll
        for (int i = 0; i < 8; i++) dst[tid + 256*i] = src[tid + 256*i];
        const float4* ps = (const float4*)g_par1;
        float4* pd = (float4*)sdw1;
        pd[tid] = ps[tid];
        if (tid < 144) pd[256+tid] = ps[256+tid];
    }
    __syncthreads();

    const int p0 = blockIdx.x*256;
    const int b  = p0 >> 14;
    const int n0 = p0 & (NN-1);
    const int n  = n0 + tid;

    // ---- theta_max (thread = point) ----
    {
        float xn0[KK], xn1[KK], xn2[KK];
        const float4* dp4 = (const float4*)(p.dp + (size_t)b*3*NN*KK + (size_t)n*KK);
#pragma unroll
        for (int k4 = 0; k4 < 4; k4++) {
            float4 A = dp4[k4];
            float4 Bv= dp4[(NN*KK/4) + k4];
            float4 Cv= dp4[(2*NN*KK/4) + k4];
            float ax[4]={A.x,A.y,A.z,A.w}, bx[4]={Bv.x,Bv.y,Bv.z,Bv.w}, cx[4]={Cv.x,Cv.y,Cv.z,Cv.w};
#pragma unroll
            for (int kk = 0; kk < 4; kk++) {
                float x0=ax[kk], x1=bx[kk], x2=cx[kk];
                float inv = rsqrtf(fmaxf(x0*x0+x1*x1+x2*x2, 1e-24f));
                xn0[4*k4+kk]=x0*inv; xn1[4*k4+kk]=x1*inv; xn2[4*k4+kk]=x2*inv;
            }
        }
        float tm[MM];
        const float4* sv4 = (const float4*)svv;
#pragma unroll
        for (int m = 0; m < MM; m++) {
            float4 v = sv4[m];
            float acc = -INFINITY;
#pragma unroll
            for (int k = 0; k < KK; k++)
                acc = fmaxf(acc, v.x*xn0[k] + v.y*xn1[k] + v.z*xn2[k]);
            tm[m] = acc;
        }
        const float4* sdw1_4 = (const float4*)sdw1;
#pragma unroll
        for (int j2 = 0; j2 < HH/2; j2++) {
            float hv[2];
#pragma unroll
            for (int q = 0; q < 2; q++) {
                int j = 2*j2 + q;
                float acc = 0.f;
#pragma unroll
                for (int m4 = 0; m4 < 8; m4++) {
                    float4 w = sdw1_4[j*8 + m4];
                    acc += w.x*tm[4*m4] + w.y*tm[4*m4+1] + w.z*tm[4*m4+2] + w.w*tm[4*m4+3];
                }
                hv[q] = gelu_exact(acc*ssc1[j] + ssh1[j]);
            }
            *(unsigned*)&hA[tid*40 + 2*j2] = h2u(__floats2half2_rn(hv[0], hv[1]));
        }
    }

    // ---- stage x tile ----
    {
        const float* fb = p.f + (size_t)b*CC*NN + n;
#pragma unroll
        for (int c2 = 0; c2 < 32; c2++) {
            float v0 = fb[(size_t)(2*c2  )*NN];
            float v1 = fb[(size_t)(2*c2+1)*NN];
            *(unsigned*)&xA[tid*72 + 2*c2] = h2u(__floats2half2_rn(v0, v1));
        }
    }
    __syncthreads();

    const int w  = tid >> 5;
    const int lt = tid & 31;
    const int tq = lt >> 2;
    const int tr = lt & 3;
    const float* fg = p.f + (size_t)b*CC*NN;

#pragma unroll 1
    for (int pti = 0; pti < 2; pti++) {
        const int ptb = (w*2 + pti) * 16;
        unsigned ax[4][4], ah[2][4];
#pragma unroll
        for (int ks = 0; ks < 4; ks++) {
            int r0 = (ptb + tq)*72, r1 = r0 + 8*72;
            int k0 = 16*ks + 2*tr;
            ax[ks][0] = *(const unsigned*)&xA[r0 + k0];
            ax[ks][1] = *(const unsigned*)&xA[r1 + k0];
            ax[ks][2] = *(const unsigned*)&xA[r0 + k0 + 8];
            ax[ks][3] = *(const unsigned*)&xA[r1 + k0 + 8];
        }
#pragma unroll
        for (int ks = 0; ks < 2; ks++) {
            int r0 = (ptb + tq)*40, r1 = r0 + 8*40;
            int k0 = 16*ks + 2*tr;
            ah[ks][0] = *(const unsigned*)&hA[r0 + k0];
            ah[ks][1] = *(const unsigned*)&hA[r1 + k0];
            ah[ks][2] = *(const unsigned*)&hA[r0 + k0 + 8];
            ah[ks][3] = *(const unsigned*)&hA[r1 + k0 + 8];
        }

#pragma unroll 1
        for (int nt = 0; nt < 8; nt++) {
            const int ch0 = nt*8 + tr*2;
            float d1[4], d2[4], d3[4], dpe[4];
            d1[0]=sb1[ch0];   d1[1]=sb1[ch0+1];   d1[2]=d1[0];  d1[3]=d1[1];
            d2[0]=sb2[ch0];   d2[1]=sb2[ch0+1];   d2[2]=d2[0];  d2[3]=d2[1];
            d3[0]=sb3[ch0];   d3[1]=sb3[ch0+1];   d3[2]=d3[0];  d3[3]=d3[1];
            dpe[0]=sbias2[ch0]; dpe[1]=sbias2[ch0+1]; dpe[2]=dpe[0]; dpe[3]=dpe[1];

            const int nrow = (nt*8 + tq)*72;
#pragma unroll
            for (int ks = 0; ks < 4; ks++) {
                const int kb = 16*ks + 2*tr;
                unsigned b0, b1;
                b0 = *(const unsigned*)&ws1[nrow + kb];
                b1 = *(const unsigned*)&ws1[nrow + kb + 8];
                mma16816(d1, ax[ks], b0, b1);
                b0 = *(const unsigned*)&ws2[nrow + kb];
                b1 = *(const unsigned*)&ws2[nrow + kb + 8];
                mma16816(d2, ax[ks], b0, b1);
                b0 = *(const unsigned*)&ws3[nrow + kb];
                b1 = *(const unsigned*)&ws3[nrow + kb + 8];
                mma16816(d3, ax[ks], b0, b1);
            }
            const int drow = (nt*8 + tq)*40;
#pragma unroll
            for (int ks = 0; ks < 2; ks++) {
                const int kb = 16*ks + 2*tr;
                unsigned b0 = *(const unsigned*)&dws[drow + kb];
                unsigned b1 = *(const unsigned*)&dws[drow + kb + 8];
                mma16816(dpe, ah[ks], b0, b1);
            }

#pragma unroll
            for (int r = 0; r < 2; r++) {
                const int lpt = ptb + tq + 8*r;
                const int gpt = p0 + lpt;
                float f1a=d1[2*r], f1b=d1[2*r+1];
                float f2a=d2[2*r], f2b=d2[2*r+1];
                float f3a=d3[2*r], f3b=d3[2*r+1];
                float pea=dpe[2*r], peb=dpe[2*r+1];

                uint2 pk;
                pk.x = h2u(__floats2half2_rn(f1a, f1b));
                pk.y = h2u(__floats2half2_rn(f2a, f2b));
                *(uint2*)(g_f12 + (size_t)gpt*128 + 2*ch0) = pk;

                float fo0 = fg[(size_t)(ch0  )*NN + (n0 + lpt)];
                float fo1 = fg[(size_t)(ch0+1)*NN + (n0 + lpt)];
                float bx = fo0 + pea + sscA[ch0  ]*(f2a+f3a) + sshA[ch0  ];
                float by = fo1 + peb + sscA[ch0+1]*(f2b+f3b) + sshA[ch0+1];
                *(float2*)(g_base + (size_t)gpt*CC + ch0) = make_float2(bx, by);
            }
        }
    }
}

// ---------------------------------------------------------------------------
// Kernel 2: 64 points / block, 512 threads, 2 blocks/SM.
// ---------------------------------------------------------------------------
__global__ __launch_bounds__(512, 2) void k2(P2 p) {
    extern __shared__ char smb[];
    float*  sxs  = (float*)smb;                  // 64*68 fp32 x (residual)
    float*  sscM = sxs + 4352;                   // 128
    float*  sshM = sscM + 128;                   // 128
    float*  sA   = sshM + 128;                   // 64 -> params 320 floats
    __half* xh   = (__half*)(smb + 18688);       // 64*72
    __half* h2h  = xh + 4608;                    // 64*136
    __half* w1h  = h2h + 8704;                   // 128*72
    __half* w2h  = w1h + 9216;                   // 64*136 -> 81152 B

    const int tid = threadIdx.x;
    const int w = tid >> 5, l = tid & 31;

    // fast staging from preconverted globals
    {
        const uint4* src = (const uint4*)g_k2w;
        uint4* dst = (uint4*)w1h;
#pragma unroll
        for (int i = 0; i < 4; i++) dst[tid + 512*i] = src[tid + 512*i];
        if (tid < 192) dst[2048 + tid] = src[2048 + tid];
        const float4* ps = (const float4*)g_par2;
        float4* pd = (float4*)sscM;
        if (tid < 80) pd[tid] = ps[tid];
    }
    __syncthreads();

    const int p0 = blockIdx.x*64;
    const int b  = p0 >> 14;
    const int n0 = p0 & (NN-1);

    // ---- Phase A: paired-point gather + edge max (both rounds unrolled) ----
    {
        const int half = (l >> 4) & 1;
        const int c    = l & 15;
        const size_t brow = (size_t)b*NN;
        const __half2 NEG = __float2half2_rn(-65504.f);
#pragma unroll
        for (int i = 0; i < 2; i++) {
            const int lpA = w*4 + 2*i;
            const int lp  = lpA + half;
            const int pt  = p0 + lp;
            int jreg = p.qidx[(size_t)(p0 + lpA)*KK + l];   // covers both points
            __half2 m1a = NEG, m2a = NEG, m1b = NEG, m2b = NEG;
#pragma unroll
            for (int r = 0; r < KK; r++) {
                int j = __shfl_sync(0xffffffffu, jreg, (l & 16) + r);
                uint4 v = *(const uint4*)(g_f12 + ((brow + (size_t)j) << 7) + c*8);
                m1a = __hmax2(m1a, *(__half2*)&v.x);
                m2a = __hmax2(m2a, *(__half2*)&v.y);
                m1b = __hmax2(m1b, *(__half2*)&v.z);
                m2b = __hmax2(m2b, *(__half2*)&v.w);
            }
            uint4 cv = *(const uint4*)(g_f12 + ((size_t)pt << 7) + c*8);
            float2 c1a = __half22float2(*(__half2*)&cv.x);
            float2 c2a = __half22float2(*(__half2*)&cv.y);
            float2 c1b = __half22float2(*(__half2*)&cv.z);
            float2 c2b = __half22float2(*(__half2*)&cv.w);
            float2 M1a = __half22float2(m1a), M2a = __half22float2(m2a);
            float2 M1b = __half22float2(m1b), M2b = __half22float2(m2b);
            float4 bs = *(const float4*)(g_base + (size_t)pt*CC + 4*c);
            float4 sc = *(const float4*)&sA[4*c];
            float v0 = bs.x + sc.x*((M1a.x - c1a.x) + (M2a.x - c2a.x));
            float v1 = bs.y + sc.y*((M1a.y - c1a.y) + (M2a.y - c2a.y));
            float v2 = bs.z + sc.z*((M1b.x - c1b.x) + (M2b.x - c2b.x));
            float v3 = bs.w + sc.w*((M1b.y - c1b.y) + (M2b.y - c2b.y));
            *(float4*)&sxs[lp*68 + 4*c] = make_float4(v0,v1,v2,v3);
            uint2 xp;
            xp.x = h2u(__floats2half2_rn(v0, v1));
            xp.y = h2u(__floats2half2_rn(v2, v3));
            *(uint2*)&xh[lp*72 + 4*c] = xp;
        }
    }
    __syncthreads();

    const int tq = l >> 2, tr = l & 3;

    // ---- Phase B: h2 = gelu(bnM(mw1 @ x)) via HMMA ----
    {
        const int pw = w & 3;
        const int nb = w >> 2;
        const int ptb = pw*16;
        unsigned ax[4][4];
#pragma unroll
        for (int ks = 0; ks < 4; ks++) {
            int r0 = (ptb + tq)*72, r1 = r0 + 8*72;
            int k0 = 16*ks + 2*tr;
            ax[ks][0] = *(const unsigned*)&xh[r0 + k0];
            ax[ks][1] = *(const unsigned*)&xh[r1 + k0];
            ax[ks][2] = *(const unsigned*)&xh[r0 + k0 + 8];
            ax[ks][3] = *(const unsigned*)&xh[r1 + k0 + 8];
        }
#pragma unroll
        for (int nt = 0; nt < 4; nt++) {
            const int jr = nb*32 + nt*8;
            float d[4] = {0.f,0.f,0.f,0.f};
            const int nrow = (jr + tq)*72;
#pragma unroll
            for (int ks = 0; ks < 4; ks++) {
                const int kb = 16*ks + 2*tr;
                unsigned b0 = *(const unsigned*)&w1h[nrow + kb];
                unsigned b1 = *(const unsigned*)&w1h[nrow + kb + 8];
                mma16816(d, ax[ks], b0, b1);
            }
            const int j0 = jr + 2*tr;
            float sc0 = sscM[j0], sh0 = sshM[j0];
            float sc1 = sscM[j0+1], sh1 = sshM[j0+1];
            float g0 = gelu_exact(d[0]*sc0 + sh0);
            float g1 = gelu_exact(d[1]*sc1 + sh1);
            float g2 = gelu_exact(d[2]*sc0 + sh0);
            float g3 = gelu_exact(d[3]*sc1 + sh1);
            *(unsigned*)&h2h[(ptb+tq  )*136 + j0] = h2u(__floats2half2_rn(g0, g1));
            *(unsigned*)&h2h[(ptb+tq+8)*136 + j0] = h2u(__floats2half2_rn(g2, g3));
        }
    }
    __syncthreads();

    // ---- Phase C: out = x + mw2 @ h2 via HMMA ----
    {
        const int pw = w & 3;
        const int cb = w >> 2;
        const int ptb = pw*16;
        const size_t obase = (size_t)b*CC*NN;
#pragma unroll
        for (int nt = 0; nt < 2; nt++) {
            const int ch = cb*16 + nt*8;
            float d[4] = {0.f,0.f,0.f,0.f};
            const int nrow = (ch + tq)*136;
#pragma unroll
            for (int ks = 0; ks < 8; ks++) {
                const int k0 = 16*ks + 2*tr;
                unsigned a[4];
                int r0 = (ptb + tq)*136, r1 = r0 + 8*136;
                a[0] = *(const unsigned*)&h2h[r0 + k0];
                a[1] = *(const unsigned*)&h2h[r1 + k0];
                a[2] = *(const unsigned*)&h2h[r0 + k0 + 8];
                a[3] = *(const unsigned*)&h2h[r1 + k0 + 8];
                unsigned b0 = *(const unsigned*)&w2h[nrow + k0];
                unsigned b1 = *(const unsigned*)&w2h[nrow + k0 + 8];
                mma16816(d, a, b0, b1);
            }
            const int c0 = ch + 2*tr;
            float x00 = sxs[(ptb+tq  )*68 + c0];
            float x01 = sxs[(ptb+tq  )*68 + c0+1];
            float x10 = sxs[(ptb+tq+8)*68 + c0];
            float x11 = sxs[(ptb+tq+8)*68 + c0+1];
            p.out[obase + (size_t)(c0  )*NN + n0 + ptb+tq  ] = x00 + d[0];
            p.out[obase + (size_t)(c0+1)*NN + n0 + ptb+tq  ] = x01 + d[1];
            p.out[obase + (size_t)(c0  )*NN + n0 + ptb+tq+8] = x10 + d[2];
            p.out[obase + (size_t)(c0+1)*NN + n0 + ptb+tq+8] = x11 + d[3];
        }
    }
}

// ---------------------------------------------------------------------------
extern "C" void kernel_launch(void* const* d_in, const int* in_sizes, int n_in,
                              void* d_out, int out_size) {
    const float* f        = (const float*)d_in[0];
    const float* dp       = (const float*)d_in[1];
    const int*   qidx     = (const int*)  d_in[2];
    const float* dirv     = (const float*)d_in[3];
    const float* de_w1    = (const float*)d_in[4];
    const float* de_g1    = (const float*)d_in[5];
    const float* de_b1    = (const float*)d_in[6];
    const float* de_m1    = (const float*)d_in[7];
    const float* de_v1    = (const float*)d_in[8];
    const float* de_w2    = (const float*)d_in[9];
    const float* de_bias2 = (const float*)d_in[10];
    const float* w1       = (const float*)d_in[11];
    const float* b1       = (const float*)d_in[12];
    const float* w2       = (const float*)d_in[13];
    const float* b2       = (const float*)d_in[14];
    const float* w3       = (const float*)d_in[15];
    const float* b3       = (const float*)d_in[16];
    const float* agg_g    = (const float*)d_in[17];
    const float* agg_b    = (const float*)d_in[18];
    const float* agg_m    = (const float*)d_in[19];
    const float* agg_v    = (const float*)d_in[20];
    const float* mw1      = (const float*)d_in[21];
    const float* mg       = (const float*)d_in[22];
    const float* mb       = (const float*)d_in[23];
    const float* mm       = (const float*)d_in[24];
    const float* mv       = (const float*)d_in[25];
    const float* mw2      = (const float*)d_in[26];

    P0 p0;
    p0.dirv=dirv; p0.de_w1=de_w1; p0.de_g1=de_g1; p0.de_b1=de_b1; p0.de_m1=de_m1;
    p0.de_v1=de_v1; p0.de_w2=de_w2; p0.de_bias2=de_bias2;
    p0.w1=w1; p0.b1=b1; p0.w2=w2; p0.b2=b2; p0.w3=w3; p0.b3=b3;
    p0.agg_g=agg_g; p0.agg_b=agg_b; p0.agg_m=agg_m; p0.agg_v=agg_v;
    p0.mg=mg; p0.mb=mb; p0.mm=mm; p0.mv=mv; p0.mw1=mw1; p0.mw2=mw2;

    P1 p1; p1.f=f; p1.dp=dp;
    P2 p2; p2.qidx=qidx; p2.out=(float*)d_out;

    const size_t smem1 = 96512;   // bytes
    const size_t smem2 = 81152;   // bytes
    cudaFuncSetAttribute(k1, cudaFuncAttributeMaxDynamicSharedMemorySize, (int)smem1);
    cudaFuncSetAttribute(k2, cudaFuncAttributeMaxDynamicSharedMemorySize, (int)smem2);

    k0<<<32, 256>>>(p0);
    k1<<<NPTS/256, 256, smem1>>>(p1);
    k2<<<NPTS/64, 512, smem2>>>(p2);
}